// round 13
// baseline (speedup 1.0000x reference)
#include <cuda_runtime.h>
#include <cuda_bf16.h>
#include <cuda_fp16.h>
#include <math.h>
#include <stdint.h>

#define Bn 4
#define Sn 4096
#define Cn 256
#define En 256
#define Mtot (Bn * Sn)
#define QK_L2E 1.44269504088896340736f

typedef unsigned int u32;
typedef unsigned long long u64;

// ------------------------------------------------------------------
// Static device scratch (no allocation allowed)
// ------------------------------------------------------------------
__device__ __nv_bfloat16 g_xh[Mtot * Cn];
__device__ __nv_bfloat16 g_xl[Mtot * Cn];
__device__ __nv_bfloat16 g_Wth[3 * Cn * Cn];   // Wt[which][n][k]
__device__ __nv_bfloat16 g_Wtl[3 * Cn * Cn];
__device__ __half g_Qf[Mtot * Cn];             // Q fp16, pre-scaled by log2(e)
__device__ __half g_Kf[Mtot * Cn];             // K fp16
__device__ __half g_Vt[Bn * En * Sn];          // V transposed fp16: [b][e][s]

// ------------------------------------------------------------------
// helpers
// ------------------------------------------------------------------
__device__ __forceinline__ u32 smem_u32(const void* p) {
    u32 a;
    asm("{ .reg .u64 t; cvta.to.shared.u64 t, %1; cvt.u32.u64 %0, t; }"
        : "=r"(a) : "l"(p));
    return a;
}
#define SW128(o) ((o) ^ (((o) >> 3) & 0x70))

__device__ __forceinline__ void cp16(u32 dst, const void* src) {
    asm volatile("cp.async.cg.shared.global [%0], [%1], 16;" :: "r"(dst), "l"(src));
}
#define CP_COMMIT() asm volatile("cp.async.commit_group;" ::: "memory")
#define CP_WAIT(n)  asm volatile("cp.async.wait_group %0;" :: "n"(n) : "memory")

#define LDSM_X4(r0, r1, r2, r3, addr)                                        \
    asm volatile("ldmatrix.sync.aligned.m8n8.x4.shared.b16 {%0,%1,%2,%3}, [%4];" \
                 : "=r"(r0), "=r"(r1), "=r"(r2), "=r"(r3) : "r"(addr))

#define MMA_BF16(d, a, b0, b1)                                               \
    asm volatile("mma.sync.aligned.m16n8k16.row.col.f32.bf16.bf16.f32 "      \
                 "{%0,%1,%2,%3}, {%4,%5,%6,%7}, {%8,%9}, {%0,%1,%2,%3};"     \
                 : "+f"((d)[0]), "+f"((d)[1]), "+f"((d)[2]), "+f"((d)[3])    \
                 : "r"((a)[0]), "r"((a)[1]), "r"((a)[2]), "r"((a)[3]),       \
                   "r"(b0), "r"(b1))

#define MMA_F16(d, a, b0, b1)                                                \
    asm volatile("mma.sync.aligned.m16n8k16.row.col.f32.f16.f16.f32 "        \
                 "{%0,%1,%2,%3}, {%4,%5,%6,%7}, {%8,%9}, {%0,%1,%2,%3};"     \
                 : "+f"((d)[0]), "+f"((d)[1]), "+f"((d)[2]), "+f"((d)[3])    \
                 : "r"((a)[0]), "r"((a)[1]), "r"((a)[2]), "r"((a)[3]),       \
                   "r"(b0), "r"(b1))

__device__ __forceinline__ u32 h2u(float a, float b) {
    __half2 h = __floats2half2_rn(a, b);
    return *(u32*)&h;
}
__device__ __forceinline__ float ex2f(float x) {
    float r; asm("ex2.approx.f32 %0, %1;" : "=f"(r) : "f"(x)); return r;
}
__device__ __forceinline__ u32 ex2h2(u32 x) {
    asm("ex2.approx.f16x2 %0, %0;" : "+r"(x)); return x;
}
#define ONESF16 0x3C003C00u   // (1.0h, 1.0h)

// ==================================================================
// Kernel P1: split x into bf16 hi/lo planes
// ==================================================================
__global__ __launch_bounds__(256)
void split_x_kernel(const float* __restrict__ x)
{
    size_t i = ((size_t)blockIdx.x * 256 + threadIdx.x) * 4;
    float4 v = *(const float4*)&x[i];
    float a[4] = {v.x, v.y, v.z, v.w};
    union { __nv_bfloat16 h[4]; uint2 q; } H, L;
    #pragma unroll
    for (int j = 0; j < 4; ++j) {
        H.h[j] = __float2bfloat16(a[j]);
        L.h[j] = __float2bfloat16(a[j] - __bfloat162float(H.h[j]));
    }
    *(uint2*)&g_xh[i] = H.q;
    *(uint2*)&g_xl[i] = L.q;
}

// ==================================================================
// Kernel P2: transpose + split W -> Wt[which][n][k] bf16 hi/lo
// ==================================================================
__global__ __launch_bounds__(256)
void prep_w_kernel(const float* __restrict__ Wq,
                   const float* __restrict__ Wk,
                   const float* __restrict__ Wv)
{
    __shared__ float tile[32][33];
    int which = blockIdx.z;
    const float* W = (which == 0) ? Wq : (which == 1) ? Wk : Wv;
    int k0 = blockIdx.x * 32, n0 = blockIdx.y * 32;
    int tx = threadIdx.x, ty = threadIdx.y;

    #pragma unroll
    for (int j = ty; j < 32; j += 8)
        tile[j][tx] = W[(size_t)(k0 + j) * Cn + n0 + tx];
    __syncthreads();
    #pragma unroll
    for (int j = ty; j < 32; j += 8) {
        float v = tile[tx][j];     // = W[k0+tx][n0+j]
        __nv_bfloat16 hi = __float2bfloat16(v);
        __nv_bfloat16 lo = __float2bfloat16(v - __bfloat162float(hi));
        size_t o = (size_t)which * Cn * Cn + (size_t)(n0 + j) * Cn + k0 + tx;
        g_Wth[o] = hi;
        g_Wtl[o] = lo;
    }
}

// ==================================================================
// Kernel P3: QKV projection GEMM (bf16 3-term mma).
// Epilogues: Q (x log2e) / K -> fp16 planes; V -> fp16 transposed.
// ==================================================================
#define OFF_AH 0
#define OFF_AL (16*1024)
#define OFF_BH (32*1024)
#define OFF_BL (64*1024)
#define CHUNK_BYTES (96*1024)
#define SMEM_GEMM (2*CHUNK_BYTES + 1024)

__device__ __forceinline__ void load_chunk(u32 buf,
    const __nv_bfloat16* Ah, const __nv_bfloat16* Al,
    const __nv_bfloat16* Bh, const __nv_bfloat16* Bl,
    int c0, int t)
{
    #pragma unroll
    for (int j = 0; j < 4; ++j) {
        int idx = t + 256 * j; int row = idx >> 3, g = idx & 7;
        cp16(buf + OFF_AH + SW128(row*128 + g*16), Ah + (size_t)row*Cn + c0 + g*8);
    }
    #pragma unroll
    for (int j = 0; j < 4; ++j) {
        int idx = t + 256 * j; int row = idx >> 3, g = idx & 7;
        cp16(buf + OFF_AL + SW128(row*128 + g*16), Al + (size_t)row*Cn + c0 + g*8);
    }
    #pragma unroll
    for (int j = 0; j < 8; ++j) {
        int idx = t + 256 * j; int row = idx >> 3, g = idx & 7;
        cp16(buf + OFF_BH + SW128(row*128 + g*16), Bh + (size_t)row*Cn + c0 + g*8);
    }
    #pragma unroll
    for (int j = 0; j < 8; ++j) {
        int idx = t + 256 * j; int row = idx >> 3, g = idx & 7;
        cp16(buf + OFF_BL + SW128(row*128 + g*16), Bl + (size_t)row*Cn + c0 + g*8);
    }
    CP_COMMIT();
}

__global__ __launch_bounds__(256, 1)
void qkv_mma_kernel(const float* __restrict__ bq,
                    const float* __restrict__ bk,
                    const float* __restrict__ bv)
{
    extern __shared__ __align__(1024) char dsm[];
    u32 sb0  = smem_u32(dsm);
    u32 base = (sb0 + 1023) & ~1023u;
    char* alig = dsm + (base - sb0);
    int t = threadIdx.x, wid = t >> 5, lane = t & 31;
    int warp_m = wid & 1, warp_n = wid >> 1;

    int m0 = blockIdx.x * 128;
    int which = blockIdx.y;
    const float* bias = (which == 0) ? bq : (which == 1) ? bk : bv;

    const __nv_bfloat16* Ah = g_xh + (size_t)m0 * Cn;
    const __nv_bfloat16* Al = g_xl + (size_t)m0 * Cn;
    const __nv_bfloat16* Bh = g_Wth + (size_t)which * Cn * Cn;
    const __nv_bfloat16* Bl = g_Wtl + (size_t)which * Cn * Cn;

    float acc[4][8][4];
    #pragma unroll
    for (int i = 0; i < 4; ++i)
        #pragma unroll
        for (int j = 0; j < 8; ++j)
            #pragma unroll
            for (int k = 0; k < 4; ++k) acc[i][j][k] = 0.f;

    int a_row = warp_m*64 + (lane & 15);
    int a_ck  = (lane >> 4) & 1;
    int b_row = warp_n*64 + (lane & 7) + ((lane >> 4) << 3);
    int b_ck  = (lane >> 3) & 1;

    load_chunk(base, Ah, Al, Bh, Bl, 0, t);

    for (int kc = 0; kc < 4; ++kc) {
        if (kc + 1 < 4) {
            load_chunk(base + ((kc+1)&1)*CHUNK_BYTES, Ah, Al, Bh, Bl, (kc+1)*64, t);
            asm volatile("cp.async.wait_group 1;" ::: "memory");
        } else {
            asm volatile("cp.async.wait_group 0;" ::: "memory");
        }
        __syncthreads();

        u32 buf = base + (kc & 1) * CHUNK_BYTES;
        #pragma unroll
        for (int ks = 0; ks < 4; ++ks) {
            u32 ah[4][4], al[4][4];
            #pragma unroll
            for (int mt = 0; mt < 4; ++mt) {
                int off = (a_row + mt*16)*128 + (2*ks + a_ck)*16;
                u32 sw = SW128(off);
                LDSM_X4(ah[mt][0], ah[mt][1], ah[mt][2], ah[mt][3], buf + OFF_AH + sw);
                LDSM_X4(al[mt][0], al[mt][1], al[mt][2], al[mt][3], buf + OFF_AL + sw);
            }
            #pragma unroll
            for (int np = 0; np < 4; ++np) {
                int off = (b_row + np*16)*128 + (2*ks + b_ck)*16;
                u32 sw = SW128(off);
                u32 bh[4], bl[4];
                LDSM_X4(bh[0], bh[1], bh[2], bh[3], buf + OFF_BH + sw);
                LDSM_X4(bl[0], bl[1], bl[2], bl[3], buf + OFF_BL + sw);
                #pragma unroll
                for (int mt = 0; mt < 4; ++mt) {
                    #pragma unroll
                    for (int j = 0; j < 2; ++j) {
                        MMA_BF16(acc[mt][np*2+j], ah[mt], bh[2*j], bh[2*j+1]);
                        MMA_BF16(acc[mt][np*2+j], ah[mt], bl[2*j], bl[2*j+1]);
                        MMA_BF16(acc[mt][np*2+j], al[mt], bh[2*j], bh[2*j+1]);
                    }
                }
            }
        }
        __syncthreads();
    }

    // ---- epilogue ----
    int rg = warp_m*64 + (lane >> 2);
    int cg = warp_n*64 + (lane & 3) * 2;

    if (which < 2) {
        __half* Dst = (which == 0) ? g_Qf : g_Kf;
        float scl = (which == 0) ? QK_L2E : 1.0f;
        #pragma unroll
        for (int mt = 0; mt < 4; ++mt) {
            #pragma unroll
            for (int nt = 0; nt < 8; ++nt) {
                int r = rg + mt*16, c = cg + nt*8;
                float b0 = bias[c], b1 = bias[c+1];
                #pragma unroll
                for (int hv = 0; hv < 2; ++hv) {
                    int rr = r + hv*8;
                    float v0 = (acc[mt][nt][hv*2]   + b0) * scl;
                    float v1 = (acc[mt][nt][hv*2+1] + b1) * scl;
                    *(u32*)&Dst[(size_t)(m0 + rr) * Cn + c] = h2u(v0, v1);
                }
            }
        }
    } else {
        // V: stage fp16 transposed [e][s] then coalesced write to g_Vt
        __half* stage = (__half*)alig;       // [256 e][136 pad]
        #pragma unroll
        for (int mt = 0; mt < 4; ++mt) {
            #pragma unroll
            for (int nt = 0; nt < 8; ++nt) {
                int r = rg + mt*16, c = cg + nt*8;
                float b0 = bias[c], b1 = bias[c+1];
                #pragma unroll
                for (int hv = 0; hv < 2; ++hv) {
                    int rr = r + hv*8;
                    stage[(c)   * 136 + rr] = __float2half_rn(acc[mt][nt][hv*2]   + b0);
                    stage[(c+1) * 136 + rr] = __float2half_rn(acc[mt][nt][hv*2+1] + b1);
                }
            }
        }
        __syncthreads();
        int b = m0 >> 12, s0 = m0 & 4095;
        #pragma unroll
        for (int i = t; i < 256 * 32; i += 256) {
            int e = i >> 5, sseg = i & 31;
            uint2 v;
            v.x = *(u32*)&stage[e*136 + sseg*4];
            v.y = *(u32*)&stage[e*136 + sseg*4 + 2];
            *(uint2*)&g_Vt[((size_t)(b * En + e)) * Sn + s0 + sseg*4] = v;
        }
    }
}

// ==================================================================
// Kernel 3: fused flash attention + sigmoid.
// M=128, TK=64, 256 threads, 8 warps x 16 q-rows.
// Q fp16 resident 64KB, K double 2x32KB, V triple 3x32KB = 224KB.
// Per tile: QK(kt) -> sync -> prefetch -> STAGGERED {PV(kt-1),
// softmax(kt)} across the two warps sharing each SMSP.
// f16x2 exp2; l via ones-MMA.
// ==================================================================
#define FK_Q  0
#define FK_K0 (64*1024)
#define FK_V0 (128*1024)
#define SMEM_FK (224*1024 + 1024)

__device__ __forceinline__ void load_k_tile(u32 base, int kb,
    const __half* Kf, int s0, int t)
{
    #pragma unroll
    for (int j = 0; j < 8; ++j) {
        int idx = t + 256*j;
        int cc = idx >> 9, rr = (idx >> 3) & 63, g = idx & 7;
        cp16(base + FK_K0 + kb*32768 + cc*8192 + SW128(rr*128 + g*16),
             Kf + (size_t)(s0 + rr)*Cn + cc*64 + g*8);
    }
    CP_COMMIT();
}

__device__ __forceinline__ void load_v_tile(u32 base, int vb,
    const __half* Vt, int s0, int t)
{
    #pragma unroll
    for (int j = 0; j < 8; ++j) {
        int idx = t + 256*j;
        int rr = idx >> 3, g = idx & 7;
        cp16(base + FK_V0 + vb*32768 + SW128(rr*128 + g*16),
             Vt + (size_t)rr*Sn + s0 + g*8);
    }
    CP_COMMIT();
}

struct SmaxState {
    float m0, m1;          // running max (log2 units)
};

__global__ __launch_bounds__(256, 1)
void flash_kernel(float* __restrict__ out)
{
    extern __shared__ __align__(1024) char dsm[];
    u32 sb0 = smem_u32(dsm);
    u32 base = (sb0 + 1023) & ~1023u;
    int t = threadIdx.x, wid = t >> 5, lane = t & 31;
    int b = blockIdx.y, m0 = blockIdx.x * 128;
    bool pv_first = ((wid >> 2) & 1) == 0;   // warps 0-3 vs 4-7 (SMSP partners)

    const __half* Qf = g_Qf + ((size_t)(b*Sn + m0))*Cn;
    const __half* Kf = g_Kf + (size_t)b*Sn*Cn;
    const __half* Vt = g_Vt + (size_t)b*En*Sn;

    // prologue loads: Q, K0, K1, V0 (4 groups)
    #pragma unroll
    for (int j = 0; j < 16; ++j) {
        int idx = t + 256*j;
        int cc = idx >> 10, rr = (idx >> 3) & 127, g = idx & 7;
        cp16(base + FK_Q + cc*16384 + SW128(rr*128 + g*16),
             Qf + (size_t)rr*Cn + cc*64 + g*8);
    }
    CP_COMMIT();
    load_k_tile(base, 0, Kf, 0, t);
    load_k_tile(base, 1, Kf, 64, t);
    load_v_tile(base, 0, Vt, 0, t);

    float o[32][4];
    #pragma unroll
    for (int i = 0; i < 32; ++i)
        #pragma unroll
        for (int j = 0; j < 4; ++j) o[i][j] = 0.f;
    float ol[4] = {0.f, 0.f, 0.f, 0.f};
    float m0r = -INFINITY, m1r = -INFINITY;
    u32 af[4][4];                          // P fragment of previous tile

    int a_row = wid*16 + (lane & 15);
    int a_ck  = (lane >> 4) & 1;
    int b_row = (lane & 7) + ((lane >> 4) << 3);
    int b_ck  = (lane >> 3) & 1;

    for (int kt = 0; kt < 64; ++kt) {
        if (kt < 63) { CP_WAIT(2); } else { CP_WAIT(1); }
        __syncthreads();

        // ---- QK(kt): 1-term fp16 ----
        u32 kbase = base + FK_K0 + (kt & 1)*32768;
        float s[8][4];
        #pragma unroll
        for (int i = 0; i < 8; ++i)
            #pragma unroll
            for (int j = 0; j < 4; ++j) s[i][j] = 0.f;

        #pragma unroll
        for (int ks = 0; ks < 16; ++ks) {
            int cc = ks >> 2, kl2 = ks & 3;
            u32 swA = SW128((u32)(a_row*128 + (2*kl2 + a_ck)*16));
            u32 aq[4];
            LDSM_X4(aq[0], aq[1], aq[2], aq[3], base + FK_Q + cc*16384 + swA);
            #pragma unroll
            for (int ng = 0; ng < 4; ++ng) {
                u32 swB = SW128((u32)((b_row + ng*16)*128 + (2*kl2 + b_ck)*16));
                u32 bh[4];
                LDSM_X4(bh[0], bh[1], bh[2], bh[3], kbase + cc*8192 + swB);
                MMA_F16(s[ng*2],   aq, bh[0], bh[1]);
                MMA_F16(s[ng*2+1], aq, bh[2], bh[3]);
            }
        }
        __syncthreads();                   // all warps done reading K(kt)

        // prefetch: K(kt+2) -> slot kt%2, V(kt+1) -> slot (kt+1)%3
        if (kt + 2 < 64) load_k_tile(base, kt & 1, Kf, (kt+2)*64, t);
        if (kt + 1 < 64) load_v_tile(base, (kt+1)%3, Vt, (kt+1)*64, t);

        u32 vbase = base + FK_V0 + ((kt + 2) % 3)*32768;  // == (kt-1)%3
        u32 pk[4][4];
        float mn0, mn1, sc0, sc1;

        // ---------- phase A / phase B, staggered across SMSP partners ----
        #pragma unroll 1
        for (int ph = 0; ph < 2; ++ph) {
            bool do_pv = (ph == 0) ? pv_first : !pv_first;
            if (do_pv) {
                // ---- PV(kt-1) ----
                if (kt > 0) {
                    #pragma unroll
                    for (int ka = 0; ka < 4; ++ka) {
                        #pragma unroll
                        for (int nb = 0; nb < 16; ++nb) {
                            u32 swV = SW128((u32)((b_row + nb*16)*128 + (2*ka + b_ck)*16));
                            u32 bf[4];
                            LDSM_X4(bf[0], bf[1], bf[2], bf[3], vbase + swV);
                            MMA_F16(o[nb*2],   af[ka], bf[0], bf[1]);
                            MMA_F16(o[nb*2+1], af[ka], bf[2], bf[3]);
                        }
                    }
                }
            } else {
                // ---- softmax(kt) scalar part: max, rescale o, exp-pack ----
                float mx0 = s[0][0], mx1 = s[0][2];
                #pragma unroll
                for (int nt = 0; nt < 8; ++nt) {
                    mx0 = fmaxf(mx0, fmaxf(s[nt][0], s[nt][1]));
                    mx1 = fmaxf(mx1, fmaxf(s[nt][2], s[nt][3]));
                }
                mx0 = fmaxf(mx0, __shfl_xor_sync(0xffffffffu, mx0, 1));
                mx0 = fmaxf(mx0, __shfl_xor_sync(0xffffffffu, mx0, 2));
                mx1 = fmaxf(mx1, __shfl_xor_sync(0xffffffffu, mx1, 1));
                mx1 = fmaxf(mx1, __shfl_xor_sync(0xffffffffu, mx1, 2));
                mn0 = fmaxf(m0r, mx0); mn1 = fmaxf(m1r, mx1);
                sc0 = ex2f(m0r - mn0); sc1 = ex2f(m1r - mn1);
                m0r = mn0; m1r = mn1;

                #pragma unroll
                for (int ka = 0; ka < 4; ++ka) {
                    pk[ka][0] = ex2h2(h2u(s[2*ka][0]   - mn0, s[2*ka][1]   - mn0));
                    pk[ka][1] = ex2h2(h2u(s[2*ka][2]   - mn1, s[2*ka][3]   - mn1));
                    pk[ka][2] = ex2h2(h2u(s[2*ka+1][0] - mn0, s[2*ka+1][1] - mn0));
                    pk[ka][3] = ex2h2(h2u(s[2*ka+1][2] - mn1, s[2*ka+1][3] - mn1));
                }
            }
        }

        // ---- rescale o/ol (after PV(kt-1) used the un-rescaled o) ----
        if (!__all_sync(0xffffffffu, (sc0 == 1.f) & (sc1 == 1.f))) {
            #pragma unroll
            for (int nb = 0; nb < 32; ++nb) {
                o[nb][0] *= sc0; o[nb][1] *= sc0;
                o[nb][2] *= sc1; o[nb][3] *= sc1;
            }
            ol[0] *= sc0; ol[1] *= sc0;
            ol[2] *= sc1; ol[3] *= sc1;
        }

        // ---- commit P(kt) fragment + l accumulation (ones-MMA) ----
        #pragma unroll
        for (int ka = 0; ka < 4; ++ka) {
            af[ka][0] = pk[ka][0]; af[ka][1] = pk[ka][1];
            af[ka][2] = pk[ka][2]; af[ka][3] = pk[ka][3];
            MMA_F16(ol, af[ka], ONESF16, ONESF16);
        }
    }

    // ---- final PV(63) ----
    CP_WAIT(0);
    __syncthreads();
    {
        u32 vbase = base + FK_V0 + (63 % 3)*32768;
        #pragma unroll
        for (int ka = 0; ka < 4; ++ka) {
            #pragma unroll
            for (int nb = 0; nb < 16; ++nb) {
                u32 swV = SW128((u32)((b_row + nb*16)*128 + (2*ka + b_ck)*16));
                u32 bf[4];
                LDSM_X4(bf[0], bf[1], bf[2], bf[3], vbase + swV);
                MMA_F16(o[nb*2],   af[ka], bf[0], bf[1]);
                MMA_F16(o[nb*2+1], af[ka], bf[2], bf[3]);
            }
        }
    }

    // ---- epilogue: normalize (l from ones-MMA), sigmoid, store ----
    float i0 = 1.f / ol[0], i1 = 1.f / ol[2];
    int row0 = m0 + wid*16 + (lane >> 2);
    float* O0 = out + ((size_t)b*Sn + row0) * En;
    #pragma unroll
    for (int nb = 0; nb < 32; ++nb) {
        int c = nb*8 + (lane & 3)*2;
        float2 v0, v1;
        v0.x = 1.f / (1.f + __expf(-o[nb][0] * i0));
        v0.y = 1.f / (1.f + __expf(-o[nb][1] * i0));
        v1.x = 1.f / (1.f + __expf(-o[nb][2] * i1));
        v1.y = 1.f / (1.f + __expf(-o[nb][3] * i1));
        *(float2*)&O0[c]          = v0;
        *(float2*)&O0[8*En + c]   = v1;
    }
}

// ==================================================================
// Launch
// ==================================================================
extern "C" void kernel_launch(void* const* d_in, const int* in_sizes, int n_in,
                              void* d_out, int out_size)
{
    const float* x  = (const float*)d_in[0];
    const float* Wq = (const float*)d_in[1];
    const float* bq = (const float*)d_in[2];
    const float* Wk = (const float*)d_in[3];
    const float* bk = (const float*)d_in[4];
    const float* Wv = (const float*)d_in[5];
    const float* bv = (const float*)d_in[6];
    float* out = (float*)d_out;

    cudaFuncSetAttribute(qkv_mma_kernel,
        cudaFuncAttributeMaxDynamicSharedMemorySize, SMEM_GEMM);
    cudaFuncSetAttribute(flash_kernel,
        cudaFuncAttributeMaxDynamicSharedMemorySize, SMEM_FK);

    split_x_kernel<<<Mtot * Cn / 1024, 256>>>(x);
    prep_w_kernel<<<dim3(8, 8, 3), dim3(32, 8)>>>(Wq, Wk, Wv);
    qkv_mma_kernel<<<dim3(128, 3), 256, SMEM_GEMM>>>(bq, bk, bv);
    flash_kernel<<<dim3(32, 4), 256, SMEM_FK>>>(out);
}

// round 14
// speedup vs baseline: 1.3425x; 1.3425x over previous
#include <cuda_runtime.h>
#include <cuda_bf16.h>
#include <cuda_fp16.h>
#include <math.h>
#include <stdint.h>

#define Bn 4
#define Sn 4096
#define Cn 256
#define En 256
#define Mtot (Bn * Sn)
#define QK_L2E 1.44269504088896340736f

typedef unsigned int u32;
typedef unsigned long long u64;

// ------------------------------------------------------------------
// Static device scratch (no allocation allowed)
// ------------------------------------------------------------------
__device__ __nv_bfloat16 g_xh[Mtot * Cn];
__device__ __nv_bfloat16 g_xl[Mtot * Cn];
__device__ __nv_bfloat16 g_Wth[3 * Cn * Cn];   // Wt[which][n][k]
__device__ __nv_bfloat16 g_Wtl[3 * Cn * Cn];
__device__ __half g_Qf[Mtot * Cn];             // Q fp16, pre-scaled by log2(e)
__device__ __half g_Kf[Mtot * Cn];             // K fp16
__device__ __half g_Vt[Bn * En * Sn];          // V transposed fp16: [b][e][s]

// ------------------------------------------------------------------
// helpers
// ------------------------------------------------------------------
__device__ __forceinline__ u32 smem_u32(const void* p) {
    u32 a;
    asm("{ .reg .u64 t; cvta.to.shared.u64 t, %1; cvt.u32.u64 %0, t; }"
        : "=r"(a) : "l"(p));
    return a;
}
#define SW128(o) ((o) ^ (((o) >> 3) & 0x70))

__device__ __forceinline__ void cp16(u32 dst, const void* src) {
    asm volatile("cp.async.cg.shared.global [%0], [%1], 16;" :: "r"(dst), "l"(src));
}
#define CP_COMMIT() asm volatile("cp.async.commit_group;" ::: "memory")
#define CP_WAIT(n)  asm volatile("cp.async.wait_group %0;" :: "n"(n) : "memory")

#define LDSM_X4(r0, r1, r2, r3, addr)                                        \
    asm volatile("ldmatrix.sync.aligned.m8n8.x4.shared.b16 {%0,%1,%2,%3}, [%4];" \
                 : "=r"(r0), "=r"(r1), "=r"(r2), "=r"(r3) : "r"(addr))

#define MMA_BF16(d, a, b0, b1)                                               \
    asm volatile("mma.sync.aligned.m16n8k16.row.col.f32.bf16.bf16.f32 "      \
                 "{%0,%1,%2,%3}, {%4,%5,%6,%7}, {%8,%9}, {%0,%1,%2,%3};"     \
                 : "+f"((d)[0]), "+f"((d)[1]), "+f"((d)[2]), "+f"((d)[3])    \
                 : "r"((a)[0]), "r"((a)[1]), "r"((a)[2]), "r"((a)[3]),       \
                   "r"(b0), "r"(b1))

#define MMA_F16(d, a, b0, b1)                                                \
    asm volatile("mma.sync.aligned.m16n8k16.row.col.f32.f16.f16.f32 "        \
                 "{%0,%1,%2,%3}, {%4,%5,%6,%7}, {%8,%9}, {%0,%1,%2,%3};"     \
                 : "+f"((d)[0]), "+f"((d)[1]), "+f"((d)[2]), "+f"((d)[3])    \
                 : "r"((a)[0]), "r"((a)[1]), "r"((a)[2]), "r"((a)[3]),       \
                   "r"(b0), "r"(b1))

__device__ __forceinline__ u32 h2u(float a, float b) {
    __half2 h = __floats2half2_rn(a, b);
    return *(u32*)&h;
}
__device__ __forceinline__ float ex2f(float x) {
    float r; asm("ex2.approx.f32 %0, %1;" : "=f"(r) : "f"(x)); return r;
}
__device__ __forceinline__ u32 ex2h2(u32 x) {
    asm("ex2.approx.f16x2 %0, %0;" : "+r"(x)); return x;
}
#define ONESF16 0x3C003C00u   // (1.0h, 1.0h)

// ==================================================================
// Kernel P1: split x into bf16 hi/lo planes
// ==================================================================
__global__ __launch_bounds__(256)
void split_x_kernel(const float* __restrict__ x)
{
    size_t i = ((size_t)blockIdx.x * 256 + threadIdx.x) * 4;
    float4 v = *(const float4*)&x[i];
    float a[4] = {v.x, v.y, v.z, v.w};
    union { __nv_bfloat16 h[4]; uint2 q; } H, L;
    #pragma unroll
    for (int j = 0; j < 4; ++j) {
        H.h[j] = __float2bfloat16(a[j]);
        L.h[j] = __float2bfloat16(a[j] - __bfloat162float(H.h[j]));
    }
    *(uint2*)&g_xh[i] = H.q;
    *(uint2*)&g_xl[i] = L.q;
}

// ==================================================================
// Kernel P2: transpose + split W -> Wt[which][n][k] bf16 hi/lo
// ==================================================================
__global__ __launch_bounds__(256)
void prep_w_kernel(const float* __restrict__ Wq,
                   const float* __restrict__ Wk,
                   const float* __restrict__ Wv)
{
    __shared__ float tile[32][33];
    int which = blockIdx.z;
    const float* W = (which == 0) ? Wq : (which == 1) ? Wk : Wv;
    int k0 = blockIdx.x * 32, n0 = blockIdx.y * 32;
    int tx = threadIdx.x, ty = threadIdx.y;

    #pragma unroll
    for (int j = ty; j < 32; j += 8)
        tile[j][tx] = W[(size_t)(k0 + j) * Cn + n0 + tx];
    __syncthreads();
    #pragma unroll
    for (int j = ty; j < 32; j += 8) {
        float v = tile[tx][j];     // = W[k0+tx][n0+j]
        __nv_bfloat16 hi = __float2bfloat16(v);
        __nv_bfloat16 lo = __float2bfloat16(v - __bfloat162float(hi));
        size_t o = (size_t)which * Cn * Cn + (size_t)(n0 + j) * Cn + k0 + tx;
        g_Wth[o] = hi;
        g_Wtl[o] = lo;
    }
}

// ==================================================================
// Kernel P3: QKV projection GEMM (bf16 3-term mma).
// Epilogues: Q (x log2e) / K -> fp16 planes; V -> fp16 transposed.
// ==================================================================
#define OFF_AH 0
#define OFF_AL (16*1024)
#define OFF_BH (32*1024)
#define OFF_BL (64*1024)
#define CHUNK_BYTES (96*1024)
#define SMEM_GEMM (2*CHUNK_BYTES + 1024)

__device__ __forceinline__ void load_chunk(u32 buf,
    const __nv_bfloat16* Ah, const __nv_bfloat16* Al,
    const __nv_bfloat16* Bh, const __nv_bfloat16* Bl,
    int c0, int t)
{
    #pragma unroll
    for (int j = 0; j < 4; ++j) {
        int idx = t + 256 * j; int row = idx >> 3, g = idx & 7;
        cp16(buf + OFF_AH + SW128(row*128 + g*16), Ah + (size_t)row*Cn + c0 + g*8);
    }
    #pragma unroll
    for (int j = 0; j < 4; ++j) {
        int idx = t + 256 * j; int row = idx >> 3, g = idx & 7;
        cp16(buf + OFF_AL + SW128(row*128 + g*16), Al + (size_t)row*Cn + c0 + g*8);
    }
    #pragma unroll
    for (int j = 0; j < 8; ++j) {
        int idx = t + 256 * j; int row = idx >> 3, g = idx & 7;
        cp16(buf + OFF_BH + SW128(row*128 + g*16), Bh + (size_t)row*Cn + c0 + g*8);
    }
    #pragma unroll
    for (int j = 0; j < 8; ++j) {
        int idx = t + 256 * j; int row = idx >> 3, g = idx & 7;
        cp16(buf + OFF_BL + SW128(row*128 + g*16), Bl + (size_t)row*Cn + c0 + g*8);
    }
    CP_COMMIT();
}

__global__ __launch_bounds__(256, 1)
void qkv_mma_kernel(const float* __restrict__ bq,
                    const float* __restrict__ bk,
                    const float* __restrict__ bv)
{
    extern __shared__ __align__(1024) char dsm[];
    u32 sb0  = smem_u32(dsm);
    u32 base = (sb0 + 1023) & ~1023u;
    char* alig = dsm + (base - sb0);
    int t = threadIdx.x, wid = t >> 5, lane = t & 31;
    int warp_m = wid & 1, warp_n = wid >> 1;

    int m0 = blockIdx.x * 128;
    int which = blockIdx.y;
    const float* bias = (which == 0) ? bq : (which == 1) ? bk : bv;

    const __nv_bfloat16* Ah = g_xh + (size_t)m0 * Cn;
    const __nv_bfloat16* Al = g_xl + (size_t)m0 * Cn;
    const __nv_bfloat16* Bh = g_Wth + (size_t)which * Cn * Cn;
    const __nv_bfloat16* Bl = g_Wtl + (size_t)which * Cn * Cn;

    float acc[4][8][4];
    #pragma unroll
    for (int i = 0; i < 4; ++i)
        #pragma unroll
        for (int j = 0; j < 8; ++j)
            #pragma unroll
            for (int k = 0; k < 4; ++k) acc[i][j][k] = 0.f;

    int a_row = warp_m*64 + (lane & 15);
    int a_ck  = (lane >> 4) & 1;
    int b_row = warp_n*64 + (lane & 7) + ((lane >> 4) << 3);
    int b_ck  = (lane >> 3) & 1;

    load_chunk(base, Ah, Al, Bh, Bl, 0, t);

    for (int kc = 0; kc < 4; ++kc) {
        if (kc + 1 < 4) {
            load_chunk(base + ((kc+1)&1)*CHUNK_BYTES, Ah, Al, Bh, Bl, (kc+1)*64, t);
            asm volatile("cp.async.wait_group 1;" ::: "memory");
        } else {
            asm volatile("cp.async.wait_group 0;" ::: "memory");
        }
        __syncthreads();

        u32 buf = base + (kc & 1) * CHUNK_BYTES;
        #pragma unroll
        for (int ks = 0; ks < 4; ++ks) {
            u32 ah[4][4], al[4][4];
            #pragma unroll
            for (int mt = 0; mt < 4; ++mt) {
                int off = (a_row + mt*16)*128 + (2*ks + a_ck)*16;
                u32 sw = SW128(off);
                LDSM_X4(ah[mt][0], ah[mt][1], ah[mt][2], ah[mt][3], buf + OFF_AH + sw);
                LDSM_X4(al[mt][0], al[mt][1], al[mt][2], al[mt][3], buf + OFF_AL + sw);
            }
            #pragma unroll
            for (int np = 0; np < 4; ++np) {
                int off = (b_row + np*16)*128 + (2*ks + b_ck)*16;
                u32 sw = SW128(off);
                u32 bh[4], bl[4];
                LDSM_X4(bh[0], bh[1], bh[2], bh[3], buf + OFF_BH + sw);
                LDSM_X4(bl[0], bl[1], bl[2], bl[3], buf + OFF_BL + sw);
                #pragma unroll
                for (int mt = 0; mt < 4; ++mt) {
                    #pragma unroll
                    for (int j = 0; j < 2; ++j) {
                        MMA_BF16(acc[mt][np*2+j], ah[mt], bh[2*j], bh[2*j+1]);
                        MMA_BF16(acc[mt][np*2+j], ah[mt], bl[2*j], bl[2*j+1]);
                        MMA_BF16(acc[mt][np*2+j], al[mt], bh[2*j], bh[2*j+1]);
                    }
                }
            }
        }
        __syncthreads();
    }

    // ---- epilogue ----
    int rg = warp_m*64 + (lane >> 2);
    int cg = warp_n*64 + (lane & 3) * 2;

    if (which < 2) {
        __half* Dst = (which == 0) ? g_Qf : g_Kf;
        float scl = (which == 0) ? QK_L2E : 1.0f;
        #pragma unroll
        for (int mt = 0; mt < 4; ++mt) {
            #pragma unroll
            for (int nt = 0; nt < 8; ++nt) {
                int r = rg + mt*16, c = cg + nt*8;
                float b0 = bias[c], b1 = bias[c+1];
                #pragma unroll
                for (int hv = 0; hv < 2; ++hv) {
                    int rr = r + hv*8;
                    float v0 = (acc[mt][nt][hv*2]   + b0) * scl;
                    float v1 = (acc[mt][nt][hv*2+1] + b1) * scl;
                    *(u32*)&Dst[(size_t)(m0 + rr) * Cn + c] = h2u(v0, v1);
                }
            }
        }
    } else {
        // V: stage fp16 transposed [e][s] then coalesced write to g_Vt
        __half* stage = (__half*)alig;       // [256 e][136 pad]
        #pragma unroll
        for (int mt = 0; mt < 4; ++mt) {
            #pragma unroll
            for (int nt = 0; nt < 8; ++nt) {
                int r = rg + mt*16, c = cg + nt*8;
                float b0 = bias[c], b1 = bias[c+1];
                #pragma unroll
                for (int hv = 0; hv < 2; ++hv) {
                    int rr = r + hv*8;
                    stage[(c)   * 136 + rr] = __float2half_rn(acc[mt][nt][hv*2]   + b0);
                    stage[(c+1) * 136 + rr] = __float2half_rn(acc[mt][nt][hv*2+1] + b1);
                }
            }
        }
        __syncthreads();
        int b = m0 >> 12, s0 = m0 & 4095;
        #pragma unroll
        for (int i = t; i < 256 * 32; i += 256) {
            int e = i >> 5, sseg = i & 31;
            uint2 v;
            v.x = *(u32*)&stage[e*136 + sseg*4];
            v.y = *(u32*)&stage[e*136 + sseg*4 + 2];
            *(uint2*)&g_Vt[((size_t)(b * En + e)) * Sn + s0 + sseg*4] = v;
        }
    }
}

// ==================================================================
// Kernel 3: fused flash attention + sigmoid.
// M=128, TK=64, 256 threads, 8 warps x 16 q-rows.
// Q fp16 resident 64KB, K double 2x32KB, V triple 3x32KB = 224KB.
// Per tile: MERGED loop {QK(kt) + PV(kt-1)} (independent chains,
// interleaved for per-warp ILP) -> sync -> prefetch -> softmax(kt).
// f16x2 exp2; l via ones-MMA.
// ==================================================================
#define FK_Q  0
#define FK_K0 (64*1024)
#define FK_V0 (128*1024)
#define SMEM_FK (224*1024 + 1024)

__device__ __forceinline__ void load_k_tile(u32 base, int kb,
    const __half* Kf, int s0, int t)
{
    #pragma unroll
    for (int j = 0; j < 8; ++j) {
        int idx = t + 256*j;
        int cc = idx >> 9, rr = (idx >> 3) & 63, g = idx & 7;
        cp16(base + FK_K0 + kb*32768 + cc*8192 + SW128(rr*128 + g*16),
             Kf + (size_t)(s0 + rr)*Cn + cc*64 + g*8);
    }
    CP_COMMIT();
}

__device__ __forceinline__ void load_v_tile(u32 base, int vb,
    const __half* Vt, int s0, int t)
{
    #pragma unroll
    for (int j = 0; j < 8; ++j) {
        int idx = t + 256*j;
        int rr = idx >> 3, g = idx & 7;
        cp16(base + FK_V0 + vb*32768 + SW128(rr*128 + g*16),
             Vt + (size_t)rr*Sn + s0 + g*8);
    }
    CP_COMMIT();
}

__global__ __launch_bounds__(256, 1)
void flash_kernel(float* __restrict__ out)
{
    extern __shared__ __align__(1024) char dsm[];
    u32 sb0 = smem_u32(dsm);
    u32 base = (sb0 + 1023) & ~1023u;
    int t = threadIdx.x, wid = t >> 5, lane = t & 31;
    int b = blockIdx.y, m0 = blockIdx.x * 128;

    const __half* Qf = g_Qf + ((size_t)(b*Sn + m0))*Cn;
    const __half* Kf = g_Kf + (size_t)b*Sn*Cn;
    const __half* Vt = g_Vt + (size_t)b*En*Sn;

    // prologue loads: Q, K0, K1, V0 (4 groups)
    #pragma unroll
    for (int j = 0; j < 16; ++j) {
        int idx = t + 256*j;
        int cc = idx >> 10, rr = (idx >> 3) & 127, g = idx & 7;
        cp16(base + FK_Q + cc*16384 + SW128(rr*128 + g*16),
             Qf + (size_t)rr*Cn + cc*64 + g*8);
    }
    CP_COMMIT();
    load_k_tile(base, 0, Kf, 0, t);
    load_k_tile(base, 1, Kf, 64, t);
    load_v_tile(base, 0, Vt, 0, t);

    float o[32][4];
    #pragma unroll
    for (int i = 0; i < 32; ++i)
        #pragma unroll
        for (int j = 0; j < 4; ++j) o[i][j] = 0.f;
    float ol[4] = {0.f, 0.f, 0.f, 0.f};   // row-sum accumulator via ones-MMA
    float m0r = -INFINITY, m1r = -INFINITY;
    u32 af[4][4];                          // P fragment of previous tile

    int a_row = wid*16 + (lane & 15);
    int a_ck  = (lane >> 4) & 1;
    int b_row = (lane & 7) + ((lane >> 4) << 3);
    int b_ck  = (lane >> 3) & 1;

    for (int kt = 0; kt < 64; ++kt) {
        // need K(kt), V(kt-1); pending allowed: K(kt+1), V(kt)
        if (kt < 63) { CP_WAIT(2); } else { CP_WAIT(1); }
        __syncthreads();

        // ---- MERGED: QK(kt) interleaved with PV(kt-1) ----
        u32 kbase = base + FK_K0 + (kt & 1)*32768;
        u32 vprev = base + FK_V0 + ((kt + 2) % 3)*32768;  // == (kt-1)%3
        float s[8][4];
        #pragma unroll
        for (int i = 0; i < 8; ++i)
            #pragma unroll
            for (int j = 0; j < 4; ++j) s[i][j] = 0.f;

        #pragma unroll
        for (int ks = 0; ks < 16; ++ks) {
            int cc = ks >> 2, kl2 = ks & 3;
            // --- QK slice: 1 Q-LDSM, 4 K-LDSM, 8 MMAs into s ---
            u32 swA = SW128((u32)(a_row*128 + (2*kl2 + a_ck)*16));
            u32 aq[4];
            LDSM_X4(aq[0], aq[1], aq[2], aq[3], base + FK_Q + cc*16384 + swA);
            #pragma unroll
            for (int ng = 0; ng < 4; ++ng) {
                u32 swB = SW128((u32)((b_row + ng*16)*128 + (2*kl2 + b_ck)*16));
                u32 bh[4];
                LDSM_X4(bh[0], bh[1], bh[2], bh[3], kbase + cc*8192 + swB);
                MMA_F16(s[ng*2],   aq, bh[0], bh[1]);
                MMA_F16(s[ng*2+1], aq, bh[2], bh[3]);
            }
            // --- PV slice (independent chain): 4 V-LDSM, 8 MMAs into o ---
            if (kt > 0) {
                int ka = ks >> 2, nb0 = (ks & 3) * 4;
                #pragma unroll
                for (int nb = nb0; nb < nb0 + 4; ++nb) {
                    u32 swV = SW128((u32)((b_row + nb*16)*128 + (2*ka + b_ck)*16));
                    u32 bf[4];
                    LDSM_X4(bf[0], bf[1], bf[2], bf[3], vprev + swV);
                    MMA_F16(o[nb*2],   af[ka], bf[0], bf[1]);
                    MMA_F16(o[nb*2+1], af[ka], bf[2], bf[3]);
                }
            }
        }
        __syncthreads();                   // K(kt)+V(kt-1) fully consumed

        // prefetch: K(kt+2) -> slot kt%2, V(kt+1) -> slot (kt+1)%3
        if (kt + 2 < 64) load_k_tile(base, kt & 1, Kf, (kt+2)*64, t);
        if (kt + 1 < 64) load_v_tile(base, (kt+1)%3, Vt, (kt+1)*64, t);

        // ---- online softmax(kt), log2 domain ----
        float mx0 = s[0][0], mx1 = s[0][2];
        #pragma unroll
        for (int nt = 0; nt < 8; ++nt) {
            mx0 = fmaxf(mx0, fmaxf(s[nt][0], s[nt][1]));
            mx1 = fmaxf(mx1, fmaxf(s[nt][2], s[nt][3]));
        }
        mx0 = fmaxf(mx0, __shfl_xor_sync(0xffffffffu, mx0, 1));
        mx0 = fmaxf(mx0, __shfl_xor_sync(0xffffffffu, mx0, 2));
        mx1 = fmaxf(mx1, __shfl_xor_sync(0xffffffffu, mx1, 1));
        mx1 = fmaxf(mx1, __shfl_xor_sync(0xffffffffu, mx1, 2));
        float mn0 = fmaxf(m0r, mx0), mn1 = fmaxf(m1r, mx1);
        float sc0 = ex2f(m0r - mn0), sc1 = ex2f(m1r - mn1);
        m0r = mn0; m1r = mn1;

        if (!__all_sync(0xffffffffu, (sc0 == 1.f) & (sc1 == 1.f))) {
            #pragma unroll
            for (int nb = 0; nb < 32; ++nb) {
                o[nb][0] *= sc0; o[nb][1] *= sc0;
                o[nb][2] *= sc1; o[nb][3] *= sc1;
            }
            ol[0] *= sc0; ol[1] *= sc0;
            ol[2] *= sc1; ol[3] *= sc1;
        }

        // ---- P(kt): fp32 subtract, f16x2 pack + exp2 -> A-fragment ----
        #pragma unroll
        for (int ka = 0; ka < 4; ++ka) {
            af[ka][0] = ex2h2(h2u(s[2*ka][0]   - mn0, s[2*ka][1]   - mn0));
            af[ka][1] = ex2h2(h2u(s[2*ka][2]   - mn1, s[2*ka][3]   - mn1));
            af[ka][2] = ex2h2(h2u(s[2*ka+1][0] - mn0, s[2*ka+1][1] - mn0));
            af[ka][3] = ex2h2(h2u(s[2*ka+1][2] - mn1, s[2*ka+1][3] - mn1));
        }

        // ---- l accumulation via ones-MMA (cross-lane row sum of P) ----
        #pragma unroll
        for (int ka = 0; ka < 4; ++ka)
            MMA_F16(ol, af[ka], ONESF16, ONESF16);
    }

    // ---- final PV(63) ----
    CP_WAIT(0);
    __syncthreads();
    {
        u32 vbase = base + FK_V0 + (63 % 3)*32768;
        #pragma unroll
        for (int ka = 0; ka < 4; ++ka) {
            #pragma unroll
            for (int nb = 0; nb < 16; ++nb) {
                u32 swV = SW128((u32)((b_row + nb*16)*128 + (2*ka + b_ck)*16));
                u32 bf[4];
                LDSM_X4(bf[0], bf[1], bf[2], bf[3], vbase + swV);
                MMA_F16(o[nb*2],   af[ka], bf[0], bf[1]);
                MMA_F16(o[nb*2+1], af[ka], bf[2], bf[3]);
            }
        }
    }

    // ---- epilogue: normalize (l from ones-MMA), sigmoid, store ----
    float i0 = 1.f / ol[0], i1 = 1.f / ol[2];
    int row0 = m0 + wid*16 + (lane >> 2);
    float* O0 = out + ((size_t)b*Sn + row0) * En;
    #pragma unroll
    for (int nb = 0; nb < 32; ++nb) {
        int c = nb*8 + (lane & 3)*2;
        float2 v0, v1;
        v0.x = 1.f / (1.f + __expf(-o[nb][0] * i0));
        v0.y = 1.f / (1.f + __expf(-o[nb][1] * i0));
        v1.x = 1.f / (1.f + __expf(-o[nb][2] * i1));
        v1.y = 1.f / (1.f + __expf(-o[nb][3] * i1));
        *(float2*)&O0[c]          = v0;
        *(float2*)&O0[8*En + c]   = v1;
    }
}

// ==================================================================
// Launch
// ==================================================================
extern "C" void kernel_launch(void* const* d_in, const int* in_sizes, int n_in,
                              void* d_out, int out_size)
{
    const float* x  = (const float*)d_in[0];
    const float* Wq = (const float*)d_in[1];
    const float* bq = (const float*)d_in[2];
    const float* Wk = (const float*)d_in[3];
    const float* bk = (const float*)d_in[4];
    const float* Wv = (const float*)d_in[5];
    const float* bv = (const float*)d_in[6];
    float* out = (float*)d_out;

    cudaFuncSetAttribute(qkv_mma_kernel,
        cudaFuncAttributeMaxDynamicSharedMemorySize, SMEM_GEMM);
    cudaFuncSetAttribute(flash_kernel,
        cudaFuncAttributeMaxDynamicSharedMemorySize, SMEM_FK);

    split_x_kernel<<<Mtot * Cn / 1024, 256>>>(x);
    prep_w_kernel<<<dim3(8, 8, 3), dim3(32, 8)>>>(Wq, Wk, Wv);
    qkv_mma_kernel<<<dim3(128, 3), 256, SMEM_GEMM>>>(bq, bk, bv);
    flash_kernel<<<dim3(32, 4), 256, SMEM_FK>>>(out);
}

// round 15
// speedup vs baseline: 1.3612x; 1.0139x over previous
#include <cuda_runtime.h>
#include <cuda_bf16.h>
#include <cuda_fp16.h>
#include <math.h>
#include <stdint.h>

#define Bn 4
#define Sn 4096
#define Cn 256
#define En 256
#define Mtot (Bn * Sn)
#define QK_L2E 1.44269504088896340736f

typedef unsigned int u32;
typedef unsigned long long u64;

// ------------------------------------------------------------------
// Static device scratch (no allocation allowed)
// ------------------------------------------------------------------
__device__ __nv_bfloat16 g_xh[Mtot * Cn];
__device__ __nv_bfloat16 g_xl[Mtot * Cn];
__device__ __nv_bfloat16 g_Wth[3 * Cn * Cn];   // Wt[which][n][k]
__device__ __nv_bfloat16 g_Wtl[3 * Cn * Cn];
__device__ __half g_Qf[Mtot * Cn];             // Q fp16, pre-scaled by log2(e)
__device__ __half g_Kf[Mtot * Cn];             // K fp16
__device__ __half g_Vt[Bn * En * Sn];          // V transposed fp16: [b][e][s]

// ------------------------------------------------------------------
// helpers
// ------------------------------------------------------------------
__device__ __forceinline__ u32 smem_u32(const void* p) {
    u32 a;
    asm("{ .reg .u64 t; cvta.to.shared.u64 t, %1; cvt.u32.u64 %0, t; }"
        : "=r"(a) : "l"(p));
    return a;
}
#define SW128(o) ((o) ^ (((o) >> 3) & 0x70))

__device__ __forceinline__ void cp16(u32 dst, const void* src) {
    asm volatile("cp.async.cg.shared.global [%0], [%1], 16;" :: "r"(dst), "l"(src));
}
#define CP_COMMIT() asm volatile("cp.async.commit_group;" ::: "memory")
#define CP_WAIT(n)  asm volatile("cp.async.wait_group %0;" :: "n"(n) : "memory")

#define LDSM_X4(r0, r1, r2, r3, addr)                                        \
    asm volatile("ldmatrix.sync.aligned.m8n8.x4.shared.b16 {%0,%1,%2,%3}, [%4];" \
                 : "=r"(r0), "=r"(r1), "=r"(r2), "=r"(r3) : "r"(addr))

#define MMA_BF16(d, a, b0, b1)                                               \
    asm volatile("mma.sync.aligned.m16n8k16.row.col.f32.bf16.bf16.f32 "      \
                 "{%0,%1,%2,%3}, {%4,%5,%6,%7}, {%8,%9}, {%0,%1,%2,%3};"     \
                 : "+f"((d)[0]), "+f"((d)[1]), "+f"((d)[2]), "+f"((d)[3])    \
                 : "r"((a)[0]), "r"((a)[1]), "r"((a)[2]), "r"((a)[3]),       \
                   "r"(b0), "r"(b1))

#define MMA_F16(d, a, b0, b1)                                                \
    asm volatile("mma.sync.aligned.m16n8k16.row.col.f32.f16.f16.f32 "        \
                 "{%0,%1,%2,%3}, {%4,%5,%6,%7}, {%8,%9}, {%0,%1,%2,%3};"     \
                 : "+f"((d)[0]), "+f"((d)[1]), "+f"((d)[2]), "+f"((d)[3])    \
                 : "r"((a)[0]), "r"((a)[1]), "r"((a)[2]), "r"((a)[3]),       \
                   "r"(b0), "r"(b1))

__device__ __forceinline__ u32 h2u(float a, float b) {
    __half2 h = __floats2half2_rn(a, b);
    return *(u32*)&h;
}
__device__ __forceinline__ float ex2f(float x) {
    float r; asm("ex2.approx.f32 %0, %1;" : "=f"(r) : "f"(x)); return r;
}
__device__ __forceinline__ u32 ex2h2(u32 x) {
    asm("ex2.approx.f16x2 %0, %0;" : "+r"(x)); return x;
}
#define ONESF16 0x3C003C00u   // (1.0h, 1.0h)

// ==================================================================
// Kernel P1: split x into bf16 hi/lo planes
// ==================================================================
__global__ __launch_bounds__(256)
void split_x_kernel(const float* __restrict__ x)
{
    size_t i = ((size_t)blockIdx.x * 256 + threadIdx.x) * 4;
    float4 v = *(const float4*)&x[i];
    float a[4] = {v.x, v.y, v.z, v.w};
    union { __nv_bfloat16 h[4]; uint2 q; } H, L;
    #pragma unroll
    for (int j = 0; j < 4; ++j) {
        H.h[j] = __float2bfloat16(a[j]);
        L.h[j] = __float2bfloat16(a[j] - __bfloat162float(H.h[j]));
    }
    *(uint2*)&g_xh[i] = H.q;
    *(uint2*)&g_xl[i] = L.q;
}

// ==================================================================
// Kernel P2: transpose + split W -> Wt[which][n][k] bf16 hi/lo
// ==================================================================
__global__ __launch_bounds__(256)
void prep_w_kernel(const float* __restrict__ Wq,
                   const float* __restrict__ Wk,
                   const float* __restrict__ Wv)
{
    __shared__ float tile[32][33];
    int which = blockIdx.z;
    const float* W = (which == 0) ? Wq : (which == 1) ? Wk : Wv;
    int k0 = blockIdx.x * 32, n0 = blockIdx.y * 32;
    int tx = threadIdx.x, ty = threadIdx.y;

    #pragma unroll
    for (int j = ty; j < 32; j += 8)
        tile[j][tx] = W[(size_t)(k0 + j) * Cn + n0 + tx];
    __syncthreads();
    #pragma unroll
    for (int j = ty; j < 32; j += 8) {
        float v = tile[tx][j];     // = W[k0+tx][n0+j]
        __nv_bfloat16 hi = __float2bfloat16(v);
        __nv_bfloat16 lo = __float2bfloat16(v - __bfloat162float(hi));
        size_t o = (size_t)which * Cn * Cn + (size_t)(n0 + j) * Cn + k0 + tx;
        g_Wth[o] = hi;
        g_Wtl[o] = lo;
    }
}

// ==================================================================
// Kernel P3: QKV projection GEMM (bf16 3-term mma).
// Epilogues: Q (x log2e) / K -> fp16 planes; V -> fp16 transposed.
// ==================================================================
#define OFF_AH 0
#define OFF_AL (16*1024)
#define OFF_BH (32*1024)
#define OFF_BL (64*1024)
#define CHUNK_BYTES (96*1024)
#define SMEM_GEMM (2*CHUNK_BYTES + 1024)

__device__ __forceinline__ void load_chunk(u32 buf,
    const __nv_bfloat16* Ah, const __nv_bfloat16* Al,
    const __nv_bfloat16* Bh, const __nv_bfloat16* Bl,
    int c0, int t)
{
    #pragma unroll
    for (int j = 0; j < 4; ++j) {
        int idx = t + 256 * j; int row = idx >> 3, g = idx & 7;
        cp16(buf + OFF_AH + SW128(row*128 + g*16), Ah + (size_t)row*Cn + c0 + g*8);
    }
    #pragma unroll
    for (int j = 0; j < 4; ++j) {
        int idx = t + 256 * j; int row = idx >> 3, g = idx & 7;
        cp16(buf + OFF_AL + SW128(row*128 + g*16), Al + (size_t)row*Cn + c0 + g*8);
    }
    #pragma unroll
    for (int j = 0; j < 8; ++j) {
        int idx = t + 256 * j; int row = idx >> 3, g = idx & 7;
        cp16(buf + OFF_BH + SW128(row*128 + g*16), Bh + (size_t)row*Cn + c0 + g*8);
    }
    #pragma unroll
    for (int j = 0; j < 8; ++j) {
        int idx = t + 256 * j; int row = idx >> 3, g = idx & 7;
        cp16(buf + OFF_BL + SW128(row*128 + g*16), Bl + (size_t)row*Cn + c0 + g*8);
    }
    CP_COMMIT();
}

__global__ __launch_bounds__(256, 1)
void qkv_mma_kernel(const float* __restrict__ bq,
                    const float* __restrict__ bk,
                    const float* __restrict__ bv)
{
    extern __shared__ __align__(1024) char dsm[];
    u32 sb0  = smem_u32(dsm);
    u32 base = (sb0 + 1023) & ~1023u;
    char* alig = dsm + (base - sb0);
    int t = threadIdx.x, wid = t >> 5, lane = t & 31;
    int warp_m = wid & 1, warp_n = wid >> 1;

    int m0 = blockIdx.x * 128;
    int which = blockIdx.y;
    const float* bias = (which == 0) ? bq : (which == 1) ? bk : bv;

    const __nv_bfloat16* Ah = g_xh + (size_t)m0 * Cn;
    const __nv_bfloat16* Al = g_xl + (size_t)m0 * Cn;
    const __nv_bfloat16* Bh = g_Wth + (size_t)which * Cn * Cn;
    const __nv_bfloat16* Bl = g_Wtl + (size_t)which * Cn * Cn;

    float acc[4][8][4];
    #pragma unroll
    for (int i = 0; i < 4; ++i)
        #pragma unroll
        for (int j = 0; j < 8; ++j)
            #pragma unroll
            for (int k = 0; k < 4; ++k) acc[i][j][k] = 0.f;

    int a_row = warp_m*64 + (lane & 15);
    int a_ck  = (lane >> 4) & 1;
    int b_row = warp_n*64 + (lane & 7) + ((lane >> 4) << 3);
    int b_ck  = (lane >> 3) & 1;

    load_chunk(base, Ah, Al, Bh, Bl, 0, t);

    for (int kc = 0; kc < 4; ++kc) {
        if (kc + 1 < 4) {
            load_chunk(base + ((kc+1)&1)*CHUNK_BYTES, Ah, Al, Bh, Bl, (kc+1)*64, t);
            asm volatile("cp.async.wait_group 1;" ::: "memory");
        } else {
            asm volatile("cp.async.wait_group 0;" ::: "memory");
        }
        __syncthreads();

        u32 buf = base + (kc & 1) * CHUNK_BYTES;
        #pragma unroll
        for (int ks = 0; ks < 4; ++ks) {
            u32 ah[4][4], al[4][4];
            #pragma unroll
            for (int mt = 0; mt < 4; ++mt) {
                int off = (a_row + mt*16)*128 + (2*ks + a_ck)*16;
                u32 sw = SW128(off);
                LDSM_X4(ah[mt][0], ah[mt][1], ah[mt][2], ah[mt][3], buf + OFF_AH + sw);
                LDSM_X4(al[mt][0], al[mt][1], al[mt][2], al[mt][3], buf + OFF_AL + sw);
            }
            #pragma unroll
            for (int np = 0; np < 4; ++np) {
                int off = (b_row + np*16)*128 + (2*ks + b_ck)*16;
                u32 sw = SW128(off);
                u32 bh[4], bl[4];
                LDSM_X4(bh[0], bh[1], bh[2], bh[3], buf + OFF_BH + sw);
                LDSM_X4(bl[0], bl[1], bl[2], bl[3], buf + OFF_BL + sw);
                #pragma unroll
                for (int mt = 0; mt < 4; ++mt) {
                    #pragma unroll
                    for (int j = 0; j < 2; ++j) {
                        MMA_BF16(acc[mt][np*2+j], ah[mt], bh[2*j], bh[2*j+1]);
                        MMA_BF16(acc[mt][np*2+j], ah[mt], bl[2*j], bl[2*j+1]);
                        MMA_BF16(acc[mt][np*2+j], al[mt], bh[2*j], bh[2*j+1]);
                    }
                }
            }
        }
        __syncthreads();
    }

    // ---- epilogue ----
    int rg = warp_m*64 + (lane >> 2);
    int cg = warp_n*64 + (lane & 3) * 2;

    if (which < 2) {
        __half* Dst = (which == 0) ? g_Qf : g_Kf;
        float scl = (which == 0) ? QK_L2E : 1.0f;
        #pragma unroll
        for (int mt = 0; mt < 4; ++mt) {
            #pragma unroll
            for (int nt = 0; nt < 8; ++nt) {
                int r = rg + mt*16, c = cg + nt*8;
                float b0 = bias[c], b1 = bias[c+1];
                #pragma unroll
                for (int hv = 0; hv < 2; ++hv) {
                    int rr = r + hv*8;
                    float v0 = (acc[mt][nt][hv*2]   + b0) * scl;
                    float v1 = (acc[mt][nt][hv*2+1] + b1) * scl;
                    *(u32*)&Dst[(size_t)(m0 + rr) * Cn + c] = h2u(v0, v1);
                }
            }
        }
    } else {
        // V: stage fp16 transposed [e][s] then coalesced write to g_Vt
        __half* stage = (__half*)alig;       // [256 e][136 pad]
        #pragma unroll
        for (int mt = 0; mt < 4; ++mt) {
            #pragma unroll
            for (int nt = 0; nt < 8; ++nt) {
                int r = rg + mt*16, c = cg + nt*8;
                float b0 = bias[c], b1 = bias[c+1];
                #pragma unroll
                for (int hv = 0; hv < 2; ++hv) {
                    int rr = r + hv*8;
                    stage[(c)   * 136 + rr] = __float2half_rn(acc[mt][nt][hv*2]   + b0);
                    stage[(c+1) * 136 + rr] = __float2half_rn(acc[mt][nt][hv*2+1] + b1);
                }
            }
        }
        __syncthreads();
        int b = m0 >> 12, s0 = m0 & 4095;
        #pragma unroll
        for (int i = t; i < 256 * 32; i += 256) {
            int e = i >> 5, sseg = i & 31;
            uint2 v;
            v.x = *(u32*)&stage[e*136 + sseg*4];
            v.y = *(u32*)&stage[e*136 + sseg*4 + 2];
            *(uint2*)&g_Vt[((size_t)(b * En + e)) * Sn + s0 + sseg*4] = v;
        }
    }
}

// ==================================================================
// Kernel 3: fused flash attention + sigmoid.
// M=128, TK=64, 256 threads, 8 warps x 16 q-rows.
// Q fp16 resident 64KB, K double 2x32KB, V triple 3x32KB = 224KB.
// Per tile: merged {QK(kt) + PV(kt-1)} with per-step LDSM batching
// (9 loads in flight before 16 MMAs) and hoisted swizzle bases.
// f16x2 exp2; l via ones-MMA.
// ==================================================================
#define FK_Q  0
#define FK_K0 (64*1024)
#define FK_V0 (128*1024)
#define SMEM_FK (224*1024 + 1024)

__device__ __forceinline__ void load_k_tile(u32 base, int kb,
    const __half* Kf, int s0, int t)
{
    #pragma unroll
    for (int j = 0; j < 8; ++j) {
        int idx = t + 256*j;
        int cc = idx >> 9, rr = (idx >> 3) & 63, g = idx & 7;
        cp16(base + FK_K0 + kb*32768 + cc*8192 + SW128(rr*128 + g*16),
             Kf + (size_t)(s0 + rr)*Cn + cc*64 + g*8);
    }
    CP_COMMIT();
}

__device__ __forceinline__ void load_v_tile(u32 base, int vb,
    const __half* Vt, int s0, int t)
{
    #pragma unroll
    for (int j = 0; j < 8; ++j) {
        int idx = t + 256*j;
        int rr = idx >> 3, g = idx & 7;
        cp16(base + FK_V0 + vb*32768 + SW128(rr*128 + g*16),
             Vt + (size_t)rr*Sn + s0 + g*8);
    }
    CP_COMMIT();
}

__global__ __launch_bounds__(256, 1)
void flash_kernel(float* __restrict__ out)
{
    extern __shared__ __align__(1024) char dsm[];
    u32 sb0 = smem_u32(dsm);
    u32 base = (sb0 + 1023) & ~1023u;
    int t = threadIdx.x, wid = t >> 5, lane = t & 31;
    int b = blockIdx.y, m0 = blockIdx.x * 128;

    const __half* Qf = g_Qf + ((size_t)(b*Sn + m0))*Cn;
    const __half* Kf = g_Kf + (size_t)b*Sn*Cn;
    const __half* Vt = g_Vt + (size_t)b*En*Sn;

    // prologue loads: Q, K0, K1, V0 (4 groups)
    #pragma unroll
    for (int j = 0; j < 16; ++j) {
        int idx = t + 256*j;
        int cc = idx >> 10, rr = (idx >> 3) & 127, g = idx & 7;
        cp16(base + FK_Q + cc*16384 + SW128(rr*128 + g*16),
             Qf + (size_t)rr*Cn + cc*64 + g*8);
    }
    CP_COMMIT();
    load_k_tile(base, 0, Kf, 0, t);
    load_k_tile(base, 1, Kf, 64, t);
    load_v_tile(base, 0, Vt, 0, t);

    float o[32][4];
    #pragma unroll
    for (int i = 0; i < 32; ++i)
        #pragma unroll
        for (int j = 0; j < 4; ++j) o[i][j] = 0.f;
    float ol[4] = {0.f, 0.f, 0.f, 0.f};   // row-sum accumulator via ones-MMA
    float m0r = -INFINITY, m1r = -INFINITY;
    u32 af[4][4];                          // P fragment of previous tile

    int a_row = wid*16 + (lane & 15);
    int a_ck  = (lane >> 4) & 1;
    int b_row = (lane & 7) + ((lane >> 4) << 3);
    int b_ck  = (lane >> 3) & 1;

    // hoisted swizzle inner bases (lane constants; strides >= 2048 are
    // outside SW128's XOR window so they add linearly)
    u32 swQb[4], swKb[4];
    #pragma unroll
    for (int k2 = 0; k2 < 4; ++k2) {
        swQb[k2] = SW128((u32)(a_row*128 + (2*k2 + a_ck)*16));
        swKb[k2] = SW128((u32)(b_row*128 + (2*k2 + b_ck)*16));
    }

    for (int kt = 0; kt < 64; ++kt) {
        // need K(kt), V(kt-1); pending allowed: K(kt+1), V(kt)
        if (kt < 63) { CP_WAIT(2); } else { CP_WAIT(1); }
        __syncthreads();

        // ---- MERGED: QK(kt) + PV(kt-1), batched loads per step ----
        u32 kbase = base + FK_K0 + (kt & 1)*32768;
        u32 vprev = base + FK_V0 + ((kt + 2) % 3)*32768;  // == (kt-1)%3
        float s[8][4];
        #pragma unroll
        for (int i = 0; i < 8; ++i)
            #pragma unroll
            for (int j = 0; j < 4; ++j) s[i][j] = 0.f;

        #pragma unroll
        for (int ks = 0; ks < 16; ++ks) {
            int cc = ks >> 2, kl2 = ks & 3;
            int ka = cc, nb0 = kl2 * 4;
            // --- issue ALL loads for this step first (9 LDSMs) ---
            u32 aq[4];
            LDSM_X4(aq[0], aq[1], aq[2], aq[3],
                    base + FK_Q + cc*16384 + swQb[kl2]);
            u32 bh[4][4];
            #pragma unroll
            for (int ng = 0; ng < 4; ++ng)
                LDSM_X4(bh[ng][0], bh[ng][1], bh[ng][2], bh[ng][3],
                        kbase + cc*8192 + ng*2048 + swKb[kl2]);
            u32 bf[4][4];
            if (kt > 0) {
                #pragma unroll
                for (int j = 0; j < 4; ++j)
                    LDSM_X4(bf[j][0], bf[j][1], bf[j][2], bf[j][3],
                            vprev + (nb0 + j)*2048 + swKb[ka]);
            }
            // --- then the 16 MMAs, alternating the two chains ---
            #pragma unroll
            for (int ng = 0; ng < 4; ++ng) {
                MMA_F16(s[ng*2],   aq, bh[ng][0], bh[ng][1]);
                MMA_F16(s[ng*2+1], aq, bh[ng][2], bh[ng][3]);
                if (kt > 0) {
                    int nb = nb0 + ng;
                    MMA_F16(o[nb*2],   af[ka], bf[ng][0], bf[ng][1]);
                    MMA_F16(o[nb*2+1], af[ka], bf[ng][2], bf[ng][3]);
                }
            }
        }
        __syncthreads();                   // K(kt)+V(kt-1) fully consumed

        // prefetch: K(kt+2) -> slot kt%2, V(kt+1) -> slot (kt+1)%3
        if (kt + 2 < 64) load_k_tile(base, kt & 1, Kf, (kt+2)*64, t);
        if (kt + 1 < 64) load_v_tile(base, (kt+1)%3, Vt, (kt+1)*64, t);

        // ---- online softmax(kt), log2 domain ----
        float mx0 = s[0][0], mx1 = s[0][2];
        #pragma unroll
        for (int nt = 0; nt < 8; ++nt) {
            mx0 = fmaxf(mx0, fmaxf(s[nt][0], s[nt][1]));
            mx1 = fmaxf(mx1, fmaxf(s[nt][2], s[nt][3]));
        }
        mx0 = fmaxf(mx0, __shfl_xor_sync(0xffffffffu, mx0, 1));
        mx0 = fmaxf(mx0, __shfl_xor_sync(0xffffffffu, mx0, 2));
        mx1 = fmaxf(mx1, __shfl_xor_sync(0xffffffffu, mx1, 1));
        mx1 = fmaxf(mx1, __shfl_xor_sync(0xffffffffu, mx1, 2));
        float mn0 = fmaxf(m0r, mx0), mn1 = fmaxf(m1r, mx1);
        float sc0 = ex2f(m0r - mn0), sc1 = ex2f(m1r - mn1);
        m0r = mn0; m1r = mn1;

        if (!__all_sync(0xffffffffu, (sc0 == 1.f) & (sc1 == 1.f))) {
            #pragma unroll
            for (int nb = 0; nb < 32; ++nb) {
                o[nb][0] *= sc0; o[nb][1] *= sc0;
                o[nb][2] *= sc1; o[nb][3] *= sc1;
            }
            ol[0] *= sc0; ol[1] *= sc0;
            ol[2] *= sc1; ol[3] *= sc1;
        }

        // ---- P(kt): fp32 subtract, f16x2 pack + exp2 -> A-fragment ----
        #pragma unroll
        for (int ka = 0; ka < 4; ++ka) {
            af[ka][0] = ex2h2(h2u(s[2*ka][0]   - mn0, s[2*ka][1]   - mn0));
            af[ka][1] = ex2h2(h2u(s[2*ka][2]   - mn1, s[2*ka][3]   - mn1));
            af[ka][2] = ex2h2(h2u(s[2*ka+1][0] - mn0, s[2*ka+1][1] - mn0));
            af[ka][3] = ex2h2(h2u(s[2*ka+1][2] - mn1, s[2*ka+1][3] - mn1));
        }

        // ---- l accumulation via ones-MMA (cross-lane row sum of P) ----
        #pragma unroll
        for (int ka = 0; ka < 4; ++ka)
            MMA_F16(ol, af[ka], ONESF16, ONESF16);
    }

    // ---- final PV(63) ----
    CP_WAIT(0);
    __syncthreads();
    {
        u32 vbase = base + FK_V0 + (63 % 3)*32768;
        #pragma unroll
        for (int ka = 0; ka < 4; ++ka) {
            #pragma unroll
            for (int nb = 0; nb < 16; ++nb) {
                u32 bf[4];
                LDSM_X4(bf[0], bf[1], bf[2], bf[3],
                        vbase + nb*2048 + swKb[ka]);
                MMA_F16(o[nb*2],   af[ka], bf[0], bf[1]);
                MMA_F16(o[nb*2+1], af[ka], bf[2], bf[3]);
            }
        }
    }

    // ---- epilogue: normalize (l from ones-MMA), sigmoid, store ----
    float i0 = 1.f / ol[0], i1 = 1.f / ol[2];
    int row0 = m0 + wid*16 + (lane >> 2);
    float* O0 = out + ((size_t)b*Sn + row0) * En;
    #pragma unroll
    for (int nb = 0; nb < 32; ++nb) {
        int c = nb*8 + (lane & 3)*2;
        float2 v0, v1;
        v0.x = 1.f / (1.f + __expf(-o[nb][0] * i0));
        v0.y = 1.f / (1.f + __expf(-o[nb][1] * i0));
        v1.x = 1.f / (1.f + __expf(-o[nb][2] * i1));
        v1.y = 1.f / (1.f + __expf(-o[nb][3] * i1));
        *(float2*)&O0[c]          = v0;
        *(float2*)&O0[8*En + c]   = v1;
    }
}

// ==================================================================
// Launch
// ==================================================================
extern "C" void kernel_launch(void* const* d_in, const int* in_sizes, int n_in,
                              void* d_out, int out_size)
{
    const float* x  = (const float*)d_in[0];
    const float* Wq = (const float*)d_in[1];
    const float* bq = (const float*)d_in[2];
    const float* Wk = (const float*)d_in[3];
    const float* bk = (const float*)d_in[4];
    const float* Wv = (const float*)d_in[5];
    const float* bv = (const float*)d_in[6];
    float* out = (float*)d_out;

    cudaFuncSetAttribute(qkv_mma_kernel,
        cudaFuncAttributeMaxDynamicSharedMemorySize, SMEM_GEMM);
    cudaFuncSetAttribute(flash_kernel,
        cudaFuncAttributeMaxDynamicSharedMemorySize, SMEM_FK);

    split_x_kernel<<<Mtot * Cn / 1024, 256>>>(x);
    prep_w_kernel<<<dim3(8, 8, 3), dim3(32, 8)>>>(Wq, Wk, Wv);
    qkv_mma_kernel<<<dim3(128, 3), 256, SMEM_GEMM>>>(bq, bk, bv);
    flash_kernel<<<dim3(32, 4), 256, SMEM_FK>>>(out);
}

// round 16
// speedup vs baseline: 1.5205x; 1.1170x over previous
#include <cuda_runtime.h>
#include <cuda_bf16.h>
#include <cuda_fp16.h>
#include <math.h>
#include <stdint.h>

#define Bn 4
#define Sn 4096
#define Cn 256
#define En 256
#define Mtot (Bn * Sn)
#define QK_L2E 1.44269504088896340736f

typedef unsigned int u32;
typedef unsigned long long u64;

// ------------------------------------------------------------------
// Static device scratch (no allocation allowed)
// ------------------------------------------------------------------
__device__ __half g_xf[Mtot * Cn];             // x fp16
__device__ __half g_Wtf[3 * Cn * Cn];          // Wt[which][n][k] fp16
__device__ __half g_Qf[Mtot * Cn];             // Q fp16, pre-scaled by log2(e)
__device__ __half g_Kf[Mtot * Cn];             // K fp16
__device__ __half g_Vt[Bn * En * Sn];          // V transposed fp16: [b][e][s]

// ------------------------------------------------------------------
// helpers
// ------------------------------------------------------------------
__device__ __forceinline__ u32 smem_u32(const void* p) {
    u32 a;
    asm("{ .reg .u64 t; cvta.to.shared.u64 t, %1; cvt.u32.u64 %0, t; }"
        : "=r"(a) : "l"(p));
    return a;
}
#define SW128(o) ((o) ^ (((o) >> 3) & 0x70))

__device__ __forceinline__ void cp16(u32 dst, const void* src) {
    asm volatile("cp.async.cg.shared.global [%0], [%1], 16;" :: "r"(dst), "l"(src));
}
#define CP_COMMIT() asm volatile("cp.async.commit_group;" ::: "memory")
#define CP_WAIT(n)  asm volatile("cp.async.wait_group %0;" :: "n"(n) : "memory")

#define LDSM_X4(r0, r1, r2, r3, addr)                                        \
    asm volatile("ldmatrix.sync.aligned.m8n8.x4.shared.b16 {%0,%1,%2,%3}, [%4];" \
                 : "=r"(r0), "=r"(r1), "=r"(r2), "=r"(r3) : "r"(addr))

#define MMA_F16(d, a, b0, b1)                                                \
    asm volatile("mma.sync.aligned.m16n8k16.row.col.f32.f16.f16.f32 "        \
                 "{%0,%1,%2,%3}, {%4,%5,%6,%7}, {%8,%9}, {%0,%1,%2,%3};"     \
                 : "+f"((d)[0]), "+f"((d)[1]), "+f"((d)[2]), "+f"((d)[3])    \
                 : "r"((a)[0]), "r"((a)[1]), "r"((a)[2]), "r"((a)[3]),       \
                   "r"(b0), "r"(b1))

__device__ __forceinline__ u32 h2u(float a, float b) {
    __half2 h = __floats2half2_rn(a, b);
    return *(u32*)&h;
}
__device__ __forceinline__ float ex2f(float x) {
    float r; asm("ex2.approx.f32 %0, %1;" : "=f"(r) : "f"(x)); return r;
}
__device__ __forceinline__ u32 ex2h2(u32 x) {
    asm("ex2.approx.f16x2 %0, %0;" : "+r"(x)); return x;
}
#define ONESF16 0x3C003C00u   // (1.0h, 1.0h)

// ==================================================================
// Kernel P1: convert x to fp16
// ==================================================================
__global__ __launch_bounds__(256)
void split_x_kernel(const float* __restrict__ x)
{
    size_t i = ((size_t)blockIdx.x * 256 + threadIdx.x) * 8;
    float4 v0 = *(const float4*)&x[i];
    float4 v1 = *(const float4*)&x[i + 4];
    union { __half h[8]; uint4 q; } H;
    H.h[0] = __float2half_rn(v0.x); H.h[1] = __float2half_rn(v0.y);
    H.h[2] = __float2half_rn(v0.z); H.h[3] = __float2half_rn(v0.w);
    H.h[4] = __float2half_rn(v1.x); H.h[5] = __float2half_rn(v1.y);
    H.h[6] = __float2half_rn(v1.z); H.h[7] = __float2half_rn(v1.w);
    *(uint4*)&g_xf[i] = H.q;
}

// ==================================================================
// Kernel P2: transpose W -> Wt[which][n][k] fp16
// ==================================================================
__global__ __launch_bounds__(256)
void prep_w_kernel(const float* __restrict__ Wq,
                   const float* __restrict__ Wk,
                   const float* __restrict__ Wv)
{
    __shared__ float tile[32][33];
    int which = blockIdx.z;
    const float* W = (which == 0) ? Wq : (which == 1) ? Wk : Wv;
    int k0 = blockIdx.x * 32, n0 = blockIdx.y * 32;
    int tx = threadIdx.x, ty = threadIdx.y;

    #pragma unroll
    for (int j = ty; j < 32; j += 8)
        tile[j][tx] = W[(size_t)(k0 + j) * Cn + n0 + tx];
    __syncthreads();
    #pragma unroll
    for (int j = ty; j < 32; j += 8) {
        float v = tile[tx][j];     // = W[k0+tx][n0+j]
        size_t o = (size_t)which * Cn * Cn + (size_t)(n0 + j) * Cn + k0 + tx;
        g_Wtf[o] = __float2half_rn(v);
    }
}

// ==================================================================
// Kernel P3: QKV projection GEMM (fp16 single-term mma).
// Block tile 128(M) x 256(N), K=256 in 4 double-buffered 64-chunks.
// Epilogues: Q (x log2e) / K -> fp16 planes; V -> fp16 transposed.
// ==================================================================
#define QOFF_A 0
#define QOFF_B (16*1024)
#define QCHUNK (48*1024)
#define SMEM_QKV (2*QCHUNK + 1024)

__device__ __forceinline__ void load_chunk_q(u32 buf,
    const __half* A, const __half* B, int c0, int t)
{
    #pragma unroll
    for (int j = 0; j < 4; ++j) {      // A: 128 rows x 8 segs
        int idx = t + 256 * j; int row = idx >> 3, g = idx & 7;
        cp16(buf + QOFF_A + SW128(row*128 + g*16), A + (size_t)row*Cn + c0 + g*8);
    }
    #pragma unroll
    for (int j = 0; j < 8; ++j) {      // B: 256 rows x 8 segs
        int idx = t + 256 * j; int row = idx >> 3, g = idx & 7;
        cp16(buf + QOFF_B + SW128(row*128 + g*16), B + (size_t)row*Cn + c0 + g*8);
    }
    CP_COMMIT();
}

__global__ __launch_bounds__(256, 1)
void qkv_mma_kernel(const float* __restrict__ bq,
                    const float* __restrict__ bk,
                    const float* __restrict__ bv)
{
    extern __shared__ __align__(1024) char dsm[];
    u32 sb0  = smem_u32(dsm);
    u32 base = (sb0 + 1023) & ~1023u;
    char* alig = dsm + (base - sb0);
    int t = threadIdx.x, wid = t >> 5, lane = t & 31;
    int warp_m = wid & 1, warp_n = wid >> 1;

    int m0 = blockIdx.x * 128;
    int which = blockIdx.y;
    const float* bias = (which == 0) ? bq : (which == 1) ? bk : bv;

    const __half* A = g_xf + (size_t)m0 * Cn;
    const __half* B = g_Wtf + (size_t)which * Cn * Cn;

    float acc[4][8][4];
    #pragma unroll
    for (int i = 0; i < 4; ++i)
        #pragma unroll
        for (int j = 0; j < 8; ++j)
            #pragma unroll
            for (int k = 0; k < 4; ++k) acc[i][j][k] = 0.f;

    int a_row = warp_m*64 + (lane & 15);
    int a_ck  = (lane >> 4) & 1;
    int b_row = warp_n*64 + (lane & 7) + ((lane >> 4) << 3);
    int b_ck  = (lane >> 3) & 1;

    load_chunk_q(base, A, B, 0, t);

    for (int kc = 0; kc < 4; ++kc) {
        if (kc + 1 < 4) {
            load_chunk_q(base + ((kc+1)&1)*QCHUNK, A, B, (kc+1)*64, t);
            asm volatile("cp.async.wait_group 1;" ::: "memory");
        } else {
            asm volatile("cp.async.wait_group 0;" ::: "memory");
        }
        __syncthreads();

        u32 buf = base + (kc & 1) * QCHUNK;
        #pragma unroll
        for (int ks = 0; ks < 4; ++ks) {
            u32 ah[4][4];
            #pragma unroll
            for (int mt = 0; mt < 4; ++mt) {
                int off = (a_row + mt*16)*128 + (2*ks + a_ck)*16;
                LDSM_X4(ah[mt][0], ah[mt][1], ah[mt][2], ah[mt][3],
                        buf + QOFF_A + SW128(off));
            }
            #pragma unroll
            for (int np = 0; np < 4; ++np) {
                int off = (b_row + np*16)*128 + (2*ks + b_ck)*16;
                u32 bh[4];
                LDSM_X4(bh[0], bh[1], bh[2], bh[3], buf + QOFF_B + SW128(off));
                #pragma unroll
                for (int mt = 0; mt < 4; ++mt) {
                    MMA_F16(acc[mt][np*2],   ah[mt], bh[0], bh[1]);
                    MMA_F16(acc[mt][np*2+1], ah[mt], bh[2], bh[3]);
                }
            }
        }
        __syncthreads();
    }

    // ---- epilogue ----
    int rg = warp_m*64 + (lane >> 2);
    int cg = warp_n*64 + (lane & 3) * 2;

    if (which < 2) {
        __half* Dst = (which == 0) ? g_Qf : g_Kf;
        float scl = (which == 0) ? QK_L2E : 1.0f;
        #pragma unroll
        for (int mt = 0; mt < 4; ++mt) {
            #pragma unroll
            for (int nt = 0; nt < 8; ++nt) {
                int r = rg + mt*16, c = cg + nt*8;
                float b0 = bias[c], b1 = bias[c+1];
                #pragma unroll
                for (int hv = 0; hv < 2; ++hv) {
                    int rr = r + hv*8;
                    float v0 = (acc[mt][nt][hv*2]   + b0) * scl;
                    float v1 = (acc[mt][nt][hv*2+1] + b1) * scl;
                    *(u32*)&Dst[(size_t)(m0 + rr) * Cn + c] = h2u(v0, v1);
                }
            }
        }
    } else {
        // V: stage fp16 transposed [e][s] then coalesced write to g_Vt
        __half* stage = (__half*)alig;       // [256 e][136 pad]
        #pragma unroll
        for (int mt = 0; mt < 4; ++mt) {
            #pragma unroll
            for (int nt = 0; nt < 8; ++nt) {
                int r = rg + mt*16, c = cg + nt*8;
                float b0 = bias[c], b1 = bias[c+1];
                #pragma unroll
                for (int hv = 0; hv < 2; ++hv) {
                    int rr = r + hv*8;
                    stage[(c)   * 136 + rr] = __float2half_rn(acc[mt][nt][hv*2]   + b0);
                    stage[(c+1) * 136 + rr] = __float2half_rn(acc[mt][nt][hv*2+1] + b1);
                }
            }
        }
        __syncthreads();
        int b = m0 >> 12, s0 = m0 & 4095;
        #pragma unroll
        for (int i = t; i < 256 * 32; i += 256) {
            int e = i >> 5, sseg = i & 31;
            uint2 v;
            v.x = *(u32*)&stage[e*136 + sseg*4];
            v.y = *(u32*)&stage[e*136 + sseg*4 + 2];
            *(uint2*)&g_Vt[((size_t)(b * En + e)) * Sn + s0 + sseg*4] = v;
        }
    }
}

// ==================================================================
// Kernel 3: fused flash attention + sigmoid (R15 layout, unchanged).
// M=128, TK=64, 256 threads, 8 warps x 16 q-rows.
// Q fp16 resident 64KB, K double 2x32KB, V triple 3x32KB = 224KB.
// ==================================================================
#define FK_Q  0
#define FK_K0 (64*1024)
#define FK_V0 (128*1024)
#define SMEM_FK (224*1024 + 1024)

__device__ __forceinline__ void load_k_tile(u32 base, int kb,
    const __half* Kf, int s0, int t)
{
    #pragma unroll
    for (int j = 0; j < 8; ++j) {
        int idx = t + 256*j;
        int cc = idx >> 9, rr = (idx >> 3) & 63, g = idx & 7;
        cp16(base + FK_K0 + kb*32768 + cc*8192 + SW128(rr*128 + g*16),
             Kf + (size_t)(s0 + rr)*Cn + cc*64 + g*8);
    }
    CP_COMMIT();
}

__device__ __forceinline__ void load_v_tile(u32 base, int vb,
    const __half* Vt, int s0, int t)
{
    #pragma unroll
    for (int j = 0; j < 8; ++j) {
        int idx = t + 256*j;
        int rr = idx >> 3, g = idx & 7;
        cp16(base + FK_V0 + vb*32768 + SW128(rr*128 + g*16),
             Vt + (size_t)rr*Sn + s0 + g*8);
    }
    CP_COMMIT();
}

__global__ __launch_bounds__(256, 1)
void flash_kernel(float* __restrict__ out)
{
    extern __shared__ __align__(1024) char dsm[];
    u32 sb0 = smem_u32(dsm);
    u32 base = (sb0 + 1023) & ~1023u;
    int t = threadIdx.x, wid = t >> 5, lane = t & 31;
    int b = blockIdx.y, m0 = blockIdx.x * 128;

    const __half* Qf = g_Qf + ((size_t)(b*Sn + m0))*Cn;
    const __half* Kf = g_Kf + (size_t)b*Sn*Cn;
    const __half* Vt = g_Vt + (size_t)b*En*Sn;

    // prologue loads: Q, K0, K1, V0 (4 groups)
    #pragma unroll
    for (int j = 0; j < 16; ++j) {
        int idx = t + 256*j;
        int cc = idx >> 10, rr = (idx >> 3) & 127, g = idx & 7;
        cp16(base + FK_Q + cc*16384 + SW128(rr*128 + g*16),
             Qf + (size_t)rr*Cn + cc*64 + g*8);
    }
    CP_COMMIT();
    load_k_tile(base, 0, Kf, 0, t);
    load_k_tile(base, 1, Kf, 64, t);
    load_v_tile(base, 0, Vt, 0, t);

    float o[32][4];
    #pragma unroll
    for (int i = 0; i < 32; ++i)
        #pragma unroll
        for (int j = 0; j < 4; ++j) o[i][j] = 0.f;
    float ol[4] = {0.f, 0.f, 0.f, 0.f};   // row-sum accumulator via ones-MMA
    float m0r = -INFINITY, m1r = -INFINITY;
    u32 af[4][4];                          // P fragment of previous tile

    int a_row = wid*16 + (lane & 15);
    int a_ck  = (lane >> 4) & 1;
    int b_row = (lane & 7) + ((lane >> 4) << 3);
    int b_ck  = (lane >> 3) & 1;

    // hoisted swizzle inner bases
    u32 swQb[4], swKb[4];
    #pragma unroll
    for (int k2 = 0; k2 < 4; ++k2) {
        swQb[k2] = SW128((u32)(a_row*128 + (2*k2 + a_ck)*16));
        swKb[k2] = SW128((u32)(b_row*128 + (2*k2 + b_ck)*16));
    }

    for (int kt = 0; kt < 64; ++kt) {
        // need K(kt), V(kt-1); pending allowed: K(kt+1), V(kt)
        if (kt < 63) { CP_WAIT(2); } else { CP_WAIT(1); }
        __syncthreads();

        // ---- MERGED: QK(kt) + PV(kt-1), batched loads per step ----
        u32 kbase = base + FK_K0 + (kt & 1)*32768;
        u32 vprev = base + FK_V0 + ((kt + 2) % 3)*32768;  // == (kt-1)%3
        float s[8][4];
        #pragma unroll
        for (int i = 0; i < 8; ++i)
            #pragma unroll
            for (int j = 0; j < 4; ++j) s[i][j] = 0.f;

        #pragma unroll
        for (int ks = 0; ks < 16; ++ks) {
            int cc = ks >> 2, kl2 = ks & 3;
            int ka = cc, nb0 = kl2 * 4;
            // --- issue ALL loads for this step first (9 LDSMs) ---
            u32 aq[4];
            LDSM_X4(aq[0], aq[1], aq[2], aq[3],
                    base + FK_Q + cc*16384 + swQb[kl2]);
            u32 bh[4][4];
            #pragma unroll
            for (int ng = 0; ng < 4; ++ng)
                LDSM_X4(bh[ng][0], bh[ng][1], bh[ng][2], bh[ng][3],
                        kbase + cc*8192 + ng*2048 + swKb[kl2]);
            u32 bf[4][4];
            if (kt > 0) {
                #pragma unroll
                for (int j = 0; j < 4; ++j)
                    LDSM_X4(bf[j][0], bf[j][1], bf[j][2], bf[j][3],
                            vprev + (nb0 + j)*2048 + swKb[ka]);
            }
            // --- then the 16 MMAs, alternating the two chains ---
            #pragma unroll
            for (int ng = 0; ng < 4; ++ng) {
                MMA_F16(s[ng*2],   aq, bh[ng][0], bh[ng][1]);
                MMA_F16(s[ng*2+1], aq, bh[ng][2], bh[ng][3]);
                if (kt > 0) {
                    int nb = nb0 + ng;
                    MMA_F16(o[nb*2],   af[ka], bf[ng][0], bf[ng][1]);
                    MMA_F16(o[nb*2+1], af[ka], bf[ng][2], bf[ng][3]);
                }
            }
        }
        __syncthreads();                   // K(kt)+V(kt-1) fully consumed

        // prefetch: K(kt+2) -> slot kt%2, V(kt+1) -> slot (kt+1)%3
        if (kt + 2 < 64) load_k_tile(base, kt & 1, Kf, (kt+2)*64, t);
        if (kt + 1 < 64) load_v_tile(base, (kt+1)%3, Vt, (kt+1)*64, t);

        // ---- online softmax(kt), log2 domain ----
        float mx0 = s[0][0], mx1 = s[0][2];
        #pragma unroll
        for (int nt = 0; nt < 8; ++nt) {
            mx0 = fmaxf(mx0, fmaxf(s[nt][0], s[nt][1]));
            mx1 = fmaxf(mx1, fmaxf(s[nt][2], s[nt][3]));
        }
        mx0 = fmaxf(mx0, __shfl_xor_sync(0xffffffffu, mx0, 1));
        mx0 = fmaxf(mx0, __shfl_xor_sync(0xffffffffu, mx0, 2));
        mx1 = fmaxf(mx1, __shfl_xor_sync(0xffffffffu, mx1, 1));
        mx1 = fmaxf(mx1, __shfl_xor_sync(0xffffffffu, mx1, 2));
        float mn0 = fmaxf(m0r, mx0), mn1 = fmaxf(m1r, mx1);
        float sc0 = ex2f(m0r - mn0), sc1 = ex2f(m1r - mn1);
        m0r = mn0; m1r = mn1;

        if (!__all_sync(0xffffffffu, (sc0 == 1.f) & (sc1 == 1.f))) {
            #pragma unroll
            for (int nb = 0; nb < 32; ++nb) {
                o[nb][0] *= sc0; o[nb][1] *= sc0;
                o[nb][2] *= sc1; o[nb][3] *= sc1;
            }
            ol[0] *= sc0; ol[1] *= sc0;
            ol[2] *= sc1; ol[3] *= sc1;
        }

        // ---- P(kt): fp32 subtract, f16x2 pack + exp2 -> A-fragment ----
        #pragma unroll
        for (int ka = 0; ka < 4; ++ka) {
            af[ka][0] = ex2h2(h2u(s[2*ka][0]   - mn0, s[2*ka][1]   - mn0));
            af[ka][1] = ex2h2(h2u(s[2*ka][2]   - mn1, s[2*ka][3]   - mn1));
            af[ka][2] = ex2h2(h2u(s[2*ka+1][0] - mn0, s[2*ka+1][1] - mn0));
            af[ka][3] = ex2h2(h2u(s[2*ka+1][2] - mn1, s[2*ka+1][3] - mn1));
        }

        // ---- l accumulation via ones-MMA (cross-lane row sum of P) ----
        #pragma unroll
        for (int ka = 0; ka < 4; ++ka)
            MMA_F16(ol, af[ka], ONESF16, ONESF16);
    }

    // ---- final PV(63) ----
    CP_WAIT(0);
    __syncthreads();
    {
        u32 vbase = base + FK_V0 + (63 % 3)*32768;
        #pragma unroll
        for (int ka = 0; ka < 4; ++ka) {
            #pragma unroll
            for (int nb = 0; nb < 16; ++nb) {
                u32 bf[4];
                LDSM_X4(bf[0], bf[1], bf[2], bf[3],
                        vbase + nb*2048 + swKb[ka]);
                MMA_F16(o[nb*2],   af[ka], bf[0], bf[1]);
                MMA_F16(o[nb*2+1], af[ka], bf[2], bf[3]);
            }
        }
    }

    // ---- epilogue: normalize (l from ones-MMA), sigmoid, store ----
    float i0 = 1.f / ol[0], i1 = 1.f / ol[2];
    int row0 = m0 + wid*16 + (lane >> 2);
    float* O0 = out + ((size_t)b*Sn + row0) * En;
    #pragma unroll
    for (int nb = 0; nb < 32; ++nb) {
        int c = nb*8 + (lane & 3)*2;
        float2 v0, v1;
        v0.x = 1.f / (1.f + __expf(-o[nb][0] * i0));
        v0.y = 1.f / (1.f + __expf(-o[nb][1] * i0));
        v1.x = 1.f / (1.f + __expf(-o[nb][2] * i1));
        v1.y = 1.f / (1.f + __expf(-o[nb][3] * i1));
        *(float2*)&O0[c]          = v0;
        *(float2*)&O0[8*En + c]   = v1;
    }
}

// ==================================================================
// Launch
// ==================================================================
extern "C" void kernel_launch(void* const* d_in, const int* in_sizes, int n_in,
                              void* d_out, int out_size)
{
    const float* x  = (const float*)d_in[0];
    const float* Wq = (const float*)d_in[1];
    const float* bq = (const float*)d_in[2];
    const float* Wk = (const float*)d_in[3];
    const float* bk = (const float*)d_in[4];
    const float* Wv = (const float*)d_in[5];
    const float* bv = (const float*)d_in[6];
    float* out = (float*)d_out;

    cudaFuncSetAttribute(qkv_mma_kernel,
        cudaFuncAttributeMaxDynamicSharedMemorySize, SMEM_QKV);
    cudaFuncSetAttribute(flash_kernel,
        cudaFuncAttributeMaxDynamicSharedMemorySize, SMEM_FK);

    split_x_kernel<<<Mtot * Cn / 2048, 256>>>(x);
    prep_w_kernel<<<dim3(8, 8, 3), dim3(32, 8)>>>(Wq, Wk, Wv);
    qkv_mma_kernel<<<dim3(128, 3), 256, SMEM_QKV>>>(bq, bk, bv);
    flash_kernel<<<dim3(32, 4), 256, SMEM_FK>>>(out);
}

// round 17
// speedup vs baseline: 1.5532x; 1.0215x over previous
#include <cuda_runtime.h>
#include <cuda_bf16.h>
#include <cuda_fp16.h>
#include <math.h>
#include <stdint.h>

#define Bn 4
#define Sn 4096
#define Cn 256
#define En 256
#define Mtot (Bn * Sn)
#define QK_L2E 1.44269504088896340736f

typedef unsigned int u32;
typedef unsigned long long u64;

// ------------------------------------------------------------------
// Static device scratch (no allocation allowed)
// ------------------------------------------------------------------
__device__ __half g_xf[Mtot * Cn];             // x fp16
__device__ __half g_Wtf[3 * Cn * Cn];          // Wt[which][n][k] fp16
__device__ __half g_Qf[Mtot * Cn];             // Q fp16, pre-scaled by log2(e)
__device__ __half g_Kf[Mtot * Cn];             // K fp16
__device__ __half g_Vt[Bn * En * Sn];          // V transposed fp16: [b][e][s]

// ------------------------------------------------------------------
// helpers
// ------------------------------------------------------------------
__device__ __forceinline__ u32 smem_u32(const void* p) {
    u32 a;
    asm("{ .reg .u64 t; cvta.to.shared.u64 t, %1; cvt.u32.u64 %0, t; }"
        : "=r"(a) : "l"(p));
    return a;
}
#define SW128(o) ((o) ^ (((o) >> 3) & 0x70))

__device__ __forceinline__ void cp16(u32 dst, const void* src) {
    asm volatile("cp.async.cg.shared.global [%0], [%1], 16;" :: "r"(dst), "l"(src));
}
#define CP_COMMIT() asm volatile("cp.async.commit_group;" ::: "memory")
#define CP_WAIT(n)  asm volatile("cp.async.wait_group %0;" :: "n"(n) : "memory")

#define LDSM_X4(r0, r1, r2, r3, addr)                                        \
    asm volatile("ldmatrix.sync.aligned.m8n8.x4.shared.b16 {%0,%1,%2,%3}, [%4];" \
                 : "=r"(r0), "=r"(r1), "=r"(r2), "=r"(r3) : "r"(addr))

#define MMA_F16(d, a, b0, b1)                                                \
    asm volatile("mma.sync.aligned.m16n8k16.row.col.f32.f16.f16.f32 "        \
                 "{%0,%1,%2,%3}, {%4,%5,%6,%7}, {%8,%9}, {%0,%1,%2,%3};"     \
                 : "+f"((d)[0]), "+f"((d)[1]), "+f"((d)[2]), "+f"((d)[3])    \
                 : "r"((a)[0]), "r"((a)[1]), "r"((a)[2]), "r"((a)[3]),       \
                   "r"(b0), "r"(b1))

__device__ __forceinline__ u32 h2u(float a, float b) {
    __half2 h = __floats2half2_rn(a, b);
    return *(u32*)&h;
}
__device__ __forceinline__ float ex2f(float x) {
    float r; asm("ex2.approx.f32 %0, %1;" : "=f"(r) : "f"(x)); return r;
}
__device__ __forceinline__ u32 ex2h2(u32 x) {
    asm("ex2.approx.f16x2 %0, %0;" : "+r"(x)); return x;
}
#define ONESF16 0x3C003C00u   // (1.0h, 1.0h)

// ==================================================================
// Kernel P1: convert x to fp16
// ==================================================================
__global__ __launch_bounds__(256)
void split_x_kernel(const float* __restrict__ x)
{
    size_t i = ((size_t)blockIdx.x * 256 + threadIdx.x) * 8;
    float4 v0 = *(const float4*)&x[i];
    float4 v1 = *(const float4*)&x[i + 4];
    union { __half h[8]; uint4 q; } H;
    H.h[0] = __float2half_rn(v0.x); H.h[1] = __float2half_rn(v0.y);
    H.h[2] = __float2half_rn(v0.z); H.h[3] = __float2half_rn(v0.w);
    H.h[4] = __float2half_rn(v1.x); H.h[5] = __float2half_rn(v1.y);
    H.h[6] = __float2half_rn(v1.z); H.h[7] = __float2half_rn(v1.w);
    *(uint4*)&g_xf[i] = H.q;
}

// ==================================================================
// Kernel P2: transpose W -> Wt[which][n][k] fp16
// ==================================================================
__global__ __launch_bounds__(256)
void prep_w_kernel(const float* __restrict__ Wq,
                   const float* __restrict__ Wk,
                   const float* __restrict__ Wv)
{
    __shared__ float tile[32][33];
    int which = blockIdx.z;
    const float* W = (which == 0) ? Wq : (which == 1) ? Wk : Wv;
    int k0 = blockIdx.x * 32, n0 = blockIdx.y * 32;
    int tx = threadIdx.x, ty = threadIdx.y;

    #pragma unroll
    for (int j = ty; j < 32; j += 8)
        tile[j][tx] = W[(size_t)(k0 + j) * Cn + n0 + tx];
    __syncthreads();
    #pragma unroll
    for (int j = ty; j < 32; j += 8) {
        float v = tile[tx][j];     // = W[k0+tx][n0+j]
        size_t o = (size_t)which * Cn * Cn + (size_t)(n0 + j) * Cn + k0 + tx;
        g_Wtf[o] = __float2half_rn(v);
    }
}

// ==================================================================
// Kernel P3: QKV projection GEMM (fp16 single-term mma).
// ==================================================================
#define QOFF_A 0
#define QOFF_B (16*1024)
#define QCHUNK (48*1024)
#define SMEM_QKV (2*QCHUNK + 1024)

__device__ __forceinline__ void load_chunk_q(u32 buf,
    const __half* A, const __half* B, int c0, int t)
{
    #pragma unroll
    for (int j = 0; j < 4; ++j) {
        int idx = t + 256 * j; int row = idx >> 3, g = idx & 7;
        cp16(buf + QOFF_A + SW128(row*128 + g*16), A + (size_t)row*Cn + c0 + g*8);
    }
    #pragma unroll
    for (int j = 0; j < 8; ++j) {
        int idx = t + 256 * j; int row = idx >> 3, g = idx & 7;
        cp16(buf + QOFF_B + SW128(row*128 + g*16), B + (size_t)row*Cn + c0 + g*8);
    }
    CP_COMMIT();
}

__global__ __launch_bounds__(256, 1)
void qkv_mma_kernel(const float* __restrict__ bq,
                    const float* __restrict__ bk,
                    const float* __restrict__ bv)
{
    extern __shared__ __align__(1024) char dsm[];
    u32 sb0  = smem_u32(dsm);
    u32 base = (sb0 + 1023) & ~1023u;
    char* alig = dsm + (base - sb0);
    int t = threadIdx.x, wid = t >> 5, lane = t & 31;
    int warp_m = wid & 1, warp_n = wid >> 1;

    int m0 = blockIdx.x * 128;
    int which = blockIdx.y;
    const float* bias = (which == 0) ? bq : (which == 1) ? bk : bv;

    const __half* A = g_xf + (size_t)m0 * Cn;
    const __half* B = g_Wtf + (size_t)which * Cn * Cn;

    float acc[4][8][4];
    #pragma unroll
    for (int i = 0; i < 4; ++i)
        #pragma unroll
        for (int j = 0; j < 8; ++j)
            #pragma unroll
            for (int k = 0; k < 4; ++k) acc[i][j][k] = 0.f;

    int a_row = warp_m*64 + (lane & 15);
    int a_ck  = (lane >> 4) & 1;
    int b_row = warp_n*64 + (lane & 7) + ((lane >> 4) << 3);
    int b_ck  = (lane >> 3) & 1;

    load_chunk_q(base, A, B, 0, t);

    for (int kc = 0; kc < 4; ++kc) {
        if (kc + 1 < 4) {
            load_chunk_q(base + ((kc+1)&1)*QCHUNK, A, B, (kc+1)*64, t);
            asm volatile("cp.async.wait_group 1;" ::: "memory");
        } else {
            asm volatile("cp.async.wait_group 0;" ::: "memory");
        }
        __syncthreads();

        u32 buf = base + (kc & 1) * QCHUNK;
        #pragma unroll
        for (int ks = 0; ks < 4; ++ks) {
            u32 ah[4][4];
            #pragma unroll
            for (int mt = 0; mt < 4; ++mt) {
                int off = (a_row + mt*16)*128 + (2*ks + a_ck)*16;
                LDSM_X4(ah[mt][0], ah[mt][1], ah[mt][2], ah[mt][3],
                        buf + QOFF_A + SW128(off));
            }
            #pragma unroll
            for (int np = 0; np < 4; ++np) {
                int off = (b_row + np*16)*128 + (2*ks + b_ck)*16;
                u32 bh[4];
                LDSM_X4(bh[0], bh[1], bh[2], bh[3], buf + QOFF_B + SW128(off));
                #pragma unroll
                for (int mt = 0; mt < 4; ++mt) {
                    MMA_F16(acc[mt][np*2],   ah[mt], bh[0], bh[1]);
                    MMA_F16(acc[mt][np*2+1], ah[mt], bh[2], bh[3]);
                }
            }
        }
        __syncthreads();
    }

    // ---- epilogue ----
    int rg = warp_m*64 + (lane >> 2);
    int cg = warp_n*64 + (lane & 3) * 2;

    if (which < 2) {
        __half* Dst = (which == 0) ? g_Qf : g_Kf;
        float scl = (which == 0) ? QK_L2E : 1.0f;
        #pragma unroll
        for (int mt = 0; mt < 4; ++mt) {
            #pragma unroll
            for (int nt = 0; nt < 8; ++nt) {
                int r = rg + mt*16, c = cg + nt*8;
                float b0 = bias[c], b1 = bias[c+1];
                #pragma unroll
                for (int hv = 0; hv < 2; ++hv) {
                    int rr = r + hv*8;
                    float v0 = (acc[mt][nt][hv*2]   + b0) * scl;
                    float v1 = (acc[mt][nt][hv*2+1] + b1) * scl;
                    *(u32*)&Dst[(size_t)(m0 + rr) * Cn + c] = h2u(v0, v1);
                }
            }
        }
    } else {
        // V: stage fp16 transposed [e][s] then coalesced write to g_Vt
        __half* stage = (__half*)alig;       // [256 e][136 pad]
        #pragma unroll
        for (int mt = 0; mt < 4; ++mt) {
            #pragma unroll
            for (int nt = 0; nt < 8; ++nt) {
                int r = rg + mt*16, c = cg + nt*8;
                float b0 = bias[c], b1 = bias[c+1];
                #pragma unroll
                for (int hv = 0; hv < 2; ++hv) {
                    int rr = r + hv*8;
                    stage[(c)   * 136 + rr] = __float2half_rn(acc[mt][nt][hv*2]   + b0);
                    stage[(c+1) * 136 + rr] = __float2half_rn(acc[mt][nt][hv*2+1] + b1);
                }
            }
        }
        __syncthreads();
        int b = m0 >> 12, s0 = m0 & 4095;
        #pragma unroll
        for (int i = t; i < 256 * 32; i += 256) {
            int e = i >> 5, sseg = i & 31;
            uint2 v;
            v.x = *(u32*)&stage[e*136 + sseg*4];
            v.y = *(u32*)&stage[e*136 + sseg*4 + 2];
            *(uint2*)&g_Vt[((size_t)(b * En + e)) * Sn + s0 + sseg*4] = v;
        }
    }
}

// ==================================================================
// Kernel 3: fused flash attention + sigmoid.
// M=128, TK=64, 256 threads, 8 warps x 16 q-rows.
// Lazy rescale: o/ol rescale by sc(kt-1) and ones-MMA(af(kt-1))
// happen inside tile kt's merged loop, in MMA shadow; softmax keeps
// only max/shuffles/sc/exp-pack.
// ==================================================================
#define FK_Q  0
#define FK_K0 (64*1024)
#define FK_V0 (128*1024)
#define SMEM_FK (224*1024 + 1024)

__device__ __forceinline__ void load_k_tile(u32 base, int kb,
    const __half* Kf, int s0, int t)
{
    #pragma unroll
    for (int j = 0; j < 8; ++j) {
        int idx = t + 256*j;
        int cc = idx >> 9, rr = (idx >> 3) & 63, g = idx & 7;
        cp16(base + FK_K0 + kb*32768 + cc*8192 + SW128(rr*128 + g*16),
             Kf + (size_t)(s0 + rr)*Cn + cc*64 + g*8);
    }
    CP_COMMIT();
}

__device__ __forceinline__ void load_v_tile(u32 base, int vb,
    const __half* Vt, int s0, int t)
{
    #pragma unroll
    for (int j = 0; j < 8; ++j) {
        int idx = t + 256*j;
        int rr = idx >> 3, g = idx & 7;
        cp16(base + FK_V0 + vb*32768 + SW128(rr*128 + g*16),
             Vt + (size_t)rr*Sn + s0 + g*8);
    }
    CP_COMMIT();
}

__global__ __launch_bounds__(256, 1)
void flash_kernel(float* __restrict__ out)
{
    extern __shared__ __align__(1024) char dsm[];
    u32 sb0 = smem_u32(dsm);
    u32 base = (sb0 + 1023) & ~1023u;
    int t = threadIdx.x, wid = t >> 5, lane = t & 31;
    int b = blockIdx.y, m0 = blockIdx.x * 128;

    const __half* Qf = g_Qf + ((size_t)(b*Sn + m0))*Cn;
    const __half* Kf = g_Kf + (size_t)b*Sn*Cn;
    const __half* Vt = g_Vt + (size_t)b*En*Sn;

    // prologue loads: Q, K0, K1, V0 (4 groups)
    #pragma unroll
    for (int j = 0; j < 16; ++j) {
        int idx = t + 256*j;
        int cc = idx >> 10, rr = (idx >> 3) & 127, g = idx & 7;
        cp16(base + FK_Q + cc*16384 + SW128(rr*128 + g*16),
             Qf + (size_t)rr*Cn + cc*64 + g*8);
    }
    CP_COMMIT();
    load_k_tile(base, 0, Kf, 0, t);
    load_k_tile(base, 1, Kf, 64, t);
    load_v_tile(base, 0, Vt, 0, t);

    float o[32][4];
    #pragma unroll
    for (int i = 0; i < 32; ++i)
        #pragma unroll
        for (int j = 0; j < 4; ++j) o[i][j] = 0.f;
    float ol[4] = {0.f, 0.f, 0.f, 0.f};   // row-sum accumulator via ones-MMA
    float m0r = -INFINITY, m1r = -INFINITY;
    float sc0p = 1.f, sc1p = 1.f;          // pending rescale from prev tile
    u32 af[4][4];                          // P fragment of previous tile

    int a_row = wid*16 + (lane & 15);
    int a_ck  = (lane >> 4) & 1;
    int b_row = (lane & 7) + ((lane >> 4) << 3);
    int b_ck  = (lane >> 3) & 1;

    // hoisted swizzle inner bases
    u32 swQb[4], swKb[4];
    #pragma unroll
    for (int k2 = 0; k2 < 4; ++k2) {
        swQb[k2] = SW128((u32)(a_row*128 + (2*k2 + a_ck)*16));
        swKb[k2] = SW128((u32)(b_row*128 + (2*k2 + b_ck)*16));
    }

    for (int kt = 0; kt < 64; ++kt) {
        // need K(kt), V(kt-1); pending allowed: K(kt+1), V(kt)
        if (kt < 63) { CP_WAIT(2); } else { CP_WAIT(1); }
        __syncthreads();

        // ---- MERGED: QK(kt) + lazy-rescale + PV(kt-1) + ones-MMA ----
        u32 kbase = base + FK_K0 + (kt & 1)*32768;
        u32 vprev = base + FK_V0 + ((kt + 2) % 3)*32768;  // == (kt-1)%3
        float s[8][4];
        #pragma unroll
        for (int i = 0; i < 8; ++i)
            #pragma unroll
            for (int j = 0; j < 4; ++j) s[i][j] = 0.f;

        #pragma unroll
        for (int ks = 0; ks < 16; ++ks) {
            int cc = ks >> 2, kl2 = ks & 3;
            int ka = cc, nb0 = kl2 * 4;
            // --- issue all loads for this step first (9 LDSMs) ---
            u32 aq[4];
            LDSM_X4(aq[0], aq[1], aq[2], aq[3],
                    base + FK_Q + cc*16384 + swQb[kl2]);
            u32 bh[4][4];
            #pragma unroll
            for (int ng = 0; ng < 4; ++ng)
                LDSM_X4(bh[ng][0], bh[ng][1], bh[ng][2], bh[ng][3],
                        kbase + cc*8192 + ng*2048 + swKb[kl2]);
            u32 bf[4][4];
            if (kt > 0) {
                #pragma unroll
                for (int j = 0; j < 4; ++j)
                    LDSM_X4(bf[j][0], bf[j][1], bf[j][2], bf[j][3],
                            vprev + (nb0 + j)*2048 + swKb[ka]);
                // --- lazy rescale: first-touch o pairs for this step ---
                if (ks < 4) {
                    if (ks == 0) {
                        ol[0] *= sc0p; ol[1] *= sc0p;
                        ol[2] *= sc1p; ol[3] *= sc1p;
                    }
                    #pragma unroll
                    for (int q = 0; q < 4; ++q) {
                        int nbq = ks*4 + q;
                        o[nbq*2][0]   *= sc0p; o[nbq*2][1]   *= sc0p;
                        o[nbq*2][2]   *= sc1p; o[nbq*2][3]   *= sc1p;
                        o[nbq*2+1][0] *= sc0p; o[nbq*2+1][1] *= sc0p;
                        o[nbq*2+1][2] *= sc1p; o[nbq*2+1][3] *= sc1p;
                    }
                    // lazy l accumulation (one ones-MMA per early step)
                    MMA_F16(ol, af[ks], ONESF16, ONESF16);
                }
            }
            // --- 16 MMAs, alternating the two chains ---
            #pragma unroll
            for (int ng = 0; ng < 4; ++ng) {
                MMA_F16(s[ng*2],   aq, bh[ng][0], bh[ng][1]);
                MMA_F16(s[ng*2+1], aq, bh[ng][2], bh[ng][3]);
                if (kt > 0) {
                    int nb = nb0 + ng;
                    MMA_F16(o[nb*2],   af[ka], bf[ng][0], bf[ng][1]);
                    MMA_F16(o[nb*2+1], af[ka], bf[ng][2], bf[ng][3]);
                }
            }
        }
        __syncthreads();                   // K(kt)+V(kt-1) fully consumed

        // prefetch: K(kt+2) -> slot kt%2, V(kt+1) -> slot (kt+1)%3
        if (kt + 2 < 64) load_k_tile(base, kt & 1, Kf, (kt+2)*64, t);
        if (kt + 1 < 64) load_v_tile(base, (kt+1)%3, Vt, (kt+1)*64, t);

        // ---- softmax(kt), log2 domain: max + sc + exp-pack only ----
        float mx0 = s[0][0], mx1 = s[0][2];
        #pragma unroll
        for (int nt = 0; nt < 8; ++nt) {
            mx0 = fmaxf(mx0, fmaxf(s[nt][0], s[nt][1]));
            mx1 = fmaxf(mx1, fmaxf(s[nt][2], s[nt][3]));
        }
        mx0 = fmaxf(mx0, __shfl_xor_sync(0xffffffffu, mx0, 1));
        mx0 = fmaxf(mx0, __shfl_xor_sync(0xffffffffu, mx0, 2));
        mx1 = fmaxf(mx1, __shfl_xor_sync(0xffffffffu, mx1, 1));
        mx1 = fmaxf(mx1, __shfl_xor_sync(0xffffffffu, mx1, 2));
        float mn0 = fmaxf(m0r, mx0), mn1 = fmaxf(m1r, mx1);
        sc0p = ex2f(m0r - mn0); sc1p = ex2f(m1r - mn1);
        m0r = mn0; m1r = mn1;

        #pragma unroll
        for (int ka = 0; ka < 4; ++ka) {
            af[ka][0] = ex2h2(h2u(s[2*ka][0]   - mn0, s[2*ka][1]   - mn0));
            af[ka][1] = ex2h2(h2u(s[2*ka][2]   - mn1, s[2*ka][3]   - mn1));
            af[ka][2] = ex2h2(h2u(s[2*ka+1][0] - mn0, s[2*ka+1][1] - mn0));
            af[ka][3] = ex2h2(h2u(s[2*ka+1][2] - mn1, s[2*ka+1][3] - mn1));
        }
    }

    // ---- tail: apply pending rescale, final ones-MMA + PV(63) ----
    CP_WAIT(0);
    __syncthreads();
    {
        ol[0] *= sc0p; ol[1] *= sc0p; ol[2] *= sc1p; ol[3] *= sc1p;
        #pragma unroll
        for (int i = 0; i < 32; ++i) {
            o[i][0] *= sc0p; o[i][1] *= sc0p;
            o[i][2] *= sc1p; o[i][3] *= sc1p;
        }
        #pragma unroll
        for (int ka = 0; ka < 4; ++ka)
            MMA_F16(ol, af[ka], ONESF16, ONESF16);
        u32 vbase = base + FK_V0 + (63 % 3)*32768;
        #pragma unroll
        for (int ka = 0; ka < 4; ++ka) {
            #pragma unroll
            for (int nb = 0; nb < 16; ++nb) {
                u32 bf[4];
                LDSM_X4(bf[0], bf[1], bf[2], bf[3],
                        vbase + nb*2048 + swKb[ka]);
                MMA_F16(o[nb*2],   af[ka], bf[0], bf[1]);
                MMA_F16(o[nb*2+1], af[ka], bf[2], bf[3]);
            }
        }
    }

    // ---- epilogue: normalize, sigmoid (exp2 form), store ----
    float i0 = 1.f / ol[0], i1 = 1.f / ol[2];
    int row0 = m0 + wid*16 + (lane >> 2);
    float* O0 = out + ((size_t)b*Sn + row0) * En;
    #pragma unroll
    for (int nb = 0; nb < 32; ++nb) {
        int c = nb*8 + (lane & 3)*2;
        float2 v0, v1;
        v0.x = 1.f / (1.f + ex2f(-o[nb][0] * i0 * QK_L2E));
        v0.y = 1.f / (1.f + ex2f(-o[nb][1] * i0 * QK_L2E));
        v1.x = 1.f / (1.f + ex2f(-o[nb][2] * i1 * QK_L2E));
        v1.y = 1.f / (1.f + ex2f(-o[nb][3] * i1 * QK_L2E));
        *(float2*)&O0[c]          = v0;
        *(float2*)&O0[8*En + c]   = v1;
    }
}

// ==================================================================
// Launch
// ==================================================================
extern "C" void kernel_launch(void* const* d_in, const int* in_sizes, int n_in,
                              void* d_out, int out_size)
{
    const float* x  = (const float*)d_in[0];
    const float* Wq = (const float*)d_in[1];
    const float* bq = (const float*)d_in[2];
    const float* Wk = (const float*)d_in[3];
    const float* bk = (const float*)d_in[4];
    const float* Wv = (const float*)d_in[5];
    const float* bv = (const float*)d_in[6];
    float* out = (float*)d_out;

    cudaFuncSetAttribute(qkv_mma_kernel,
        cudaFuncAttributeMaxDynamicSharedMemorySize, SMEM_QKV);
    cudaFuncSetAttribute(flash_kernel,
        cudaFuncAttributeMaxDynamicSharedMemorySize, SMEM_FK);

    split_x_kernel<<<Mtot * Cn / 2048, 256>>>(x);
    prep_w_kernel<<<dim3(8, 8, 3), dim3(32, 8)>>>(Wq, Wk, Wv);
    qkv_mma_kernel<<<dim3(128, 3), 256, SMEM_QKV>>>(bq, bk, bv);
    flash_kernel<<<dim3(32, 4), 256, SMEM_FK>>>(out);
}